// round 3
// baseline (speedup 1.0000x reference)
#include <cuda_runtime.h>
#include <math.h>

#define T_ 4
#define B_ 16
#define C_ 256
#define L_ 2048
#define O_ 512
#define TBCL_ (T_*B_*C_*L_)

// z in {0, ZA, ZB}: ZA = 0.5*tanh(1), ZB = sigmoid(1)*tanh(1)
#define ZA 0.38079708f
#define ZB 0.55676994f

typedef unsigned long long u64;

__device__ __forceinline__ u64 pack2(float lo, float hi) {
    u64 d; asm("mov.b64 %0, {%1, %2};" : "=l"(d) : "f"(lo), "f"(hi)); return d;
}
__device__ __forceinline__ void unpack2(u64 v, float& lo, float& hi) {
    asm("mov.b64 {%0, %1}, %2;" : "=f"(lo), "=f"(hi) : "l"(v));
}
__device__ __forceinline__ u64 fma2(u64 a, u64 b, u64 c) {
    u64 d; asm("fma.rn.f32x2 %0, %1, %2, %3;" : "=l"(d) : "l"(a), "l"(b), "l"(c)); return d;
}

// Scratch (device globals: no allocation allowed in kernel_launch)
__device__ float g_z[TBCL_];          // 128 MB: z[t][b][c][l]
__device__ float g_proj[B_*C_];
__device__ float g_base[B_*O_];       // conv(proj) full + b_conv
__device__ float g_e0[B_*O_];         // k=0 partial (subtract at l=0)
__device__ float g_e2[B_*O_];         // k=2 partial (subtract at l=L-1)
__device__ float g_wc[3*C_*O_];       // conv weights transposed: [k][c][o]
__device__ float g_wn[C_*O_];         // [c][n] n<256: w_res, else w_skip

// ---------------- prep: proj[b][c] ----------------
__global__ void k_proj(const int* __restrict__ dstep,
                       const float* __restrict__ w1, const float* __restrict__ b1,
                       const float* __restrict__ w2, const float* __restrict__ b2,
                       const float* __restrict__ wp, const float* __restrict__ bp) {
    int b = blockIdx.x;
    int c = threadIdx.x;
    __shared__ float h[C_];
    __shared__ float emb[C_];
    float ds = (float)dstep[b];
    float t1 = ds * w1[c] + b1[c];
    float s = 1.f / (1.f + expf(-t1));
    h[c] = t1 * s;                       // silu
    __syncthreads();
    float e = b2[c];
    const float* w2r = w2 + c * C_;
    for (int j = 0; j < C_; j++) e += w2r[j] * h[j];
    __syncthreads();
    emb[c] = e;
    __syncthreads();
    float p = bp[c];
    const float* wpr = wp + c * C_;
    for (int j = 0; j < C_; j++) p += wpr[j] * emb[j];
    g_proj[b * C_ + c] = p;
}

// ---------------- prep: weight transposes ----------------
__global__ void k_wtrans(const float* __restrict__ w_conv,
                         const float* __restrict__ w_skip,
                         const float* __restrict__ w_res) {
    int i = blockIdx.x * 256 + threadIdx.x;
    if (i < 3 * C_ * O_) {
        int o = i % O_;
        int c = (i / O_) % C_;
        int k = i / (O_ * C_);
        g_wc[i] = w_conv[(o * C_ + c) * 3 + k];
    }
    if (i < C_ * O_) {
        int n = i % O_;
        int c = i / O_;
        g_wn[i] = (n < C_) ? w_res[n * C_ + c] : w_skip[(n - C_) * C_ + c];
    }
}

// ---------------- prep: conv(proj) per (b,o) + edges ----------------
__global__ void k_econv(const float* __restrict__ b_conv) {
    int b = blockIdx.x;
    int o = blockIdx.y * 128 + threadIdx.x;
    __shared__ float pr[C_];
    for (int i = threadIdx.x; i < C_; i += 128) pr[i] = g_proj[b * C_ + i];
    __syncthreads();
    float e0 = 0.f, e1 = 0.f, e2 = 0.f;
    for (int c = 0; c < C_; c++) {
        float p = pr[c];
        e0 += g_wc[(0 * C_ + c) * O_ + o] * p;
        e1 += g_wc[(1 * C_ + c) * O_ + o] * p;
        e2 += g_wc[(2 * C_ + c) * O_ + o] * p;
    }
    g_base[b * O_ + o] = e0 + e1 + e2 + b_conv[o];
    g_e0[b * O_ + o] = e0;
    g_e2[b * O_ + o] = e2;
}

// ---------------- conv1d + LIF + z (fused over T), packed f32x2 ----------------
// grid: (L/64, 4 pair-tiles, B), block 256
// block tile: 64 l positions x 64 (gate,filt) channel pairs
__global__ void __launch_bounds__(256, 2) k_conv_lif(const float* __restrict__ x) {
    const int l0 = blockIdx.x * 64;
    const int ot = blockIdx.y;            // channel-pair tile: pairs [ot*64, ot*64+64)
    const int b  = blockIdx.z;
    const int tid = threadIdx.x;
    const int tx = tid & 15;              // row group: 4 l's
    const int ty = tid >> 4;              // col group: 4 pairs
    const int r0 = tx * 4;

    __shared__ float  xs[16][66];         // 16 c x (64+2 halo) l
    __shared__ float2 ws[16][3][64];      // 16 c x 3 k x 64 (gate,filt) pairs

    float v[2][4][4];                     // [gate/filt][pair q][l]
    #pragma unroll
    for (int h = 0; h < 2; h++)
        #pragma unroll
        for (int q = 0; q < 4; q++)
            #pragma unroll
            for (int li = 0; li < 4; li++) v[h][q][li] = 0.f;

    #pragma unroll 1
    for (int t = 0; t < T_; t++) {
        u64 acc2[4][4];                   // (gate,filt) packed accumulators
        #pragma unroll
        for (int q = 0; q < 4; q++)
            #pragma unroll
            for (int li = 0; li < 4; li++) acc2[q][li] = 0ull;

        const float* xb = x + (size_t)((t * B_ + b) * C_) * L_;

        #pragma unroll 1
        for (int cc = 0; cc < C_; cc += 16) {
            // load x tile (with zero-padded halo)
            for (int i = tid; i < 16 * 66; i += 256) {
                int ci = i / 66, li = i % 66;
                int gl = l0 - 1 + li;
                float val = 0.f;
                if (gl >= 0 && gl < L_) val = xb[(cc + ci) * L_ + gl];
                xs[ci][li] = val;
            }
            // load weight tile as (gate,filt) pairs (coalesced from g_wc)
            for (int i = tid; i < 3072; i += 256) {
                int p = i & 63;
                int k = (i >> 6) % 3;
                int ci = i / 192;
                int og = ot * 64 + p;
                const float* wrow = &g_wc[(k * C_ + cc + ci) * O_];
                ws[ci][k][p] = make_float2(wrow[og], wrow[og + 256]);
            }
            __syncthreads();

            #pragma unroll
            for (int ci = 0; ci < 16; ci++) {
                u64 xx[6];
                #pragma unroll
                for (int s = 0; s < 6; s++) {
                    float xv = xs[ci][r0 + s];
                    xx[s] = pack2(xv, xv);
                }
                #pragma unroll
                for (int q = 0; q < 4; q++) {
                    int cq = ty * 4 + q;
                    u64 w0 = *(const u64*)&ws[ci][0][cq];
                    u64 w1 = *(const u64*)&ws[ci][1][cq];
                    u64 w2 = *(const u64*)&ws[ci][2][cq];
                    #pragma unroll
                    for (int li = 0; li < 4; li++) {
                        acc2[q][li] = fma2(w0, xx[li],     acc2[q][li]);
                        acc2[q][li] = fma2(w1, xx[li + 1], acc2[q][li]);
                        acc2[q][li] = fma2(w2, xx[li + 2], acc2[q][li]);
                    }
                }
            }
            __syncthreads();
        }

        // epilogue: add conv(proj)+bias (w/ edge fix), LIF step, z, store
        float* zb = g_z + (size_t)((t * B_ + b) * C_) * L_;
        #pragma unroll
        for (int q = 0; q < 4; q++) {
            int og = ot * 64 + ty * 4 + q;     // gate channel == z channel
            int of = og + 256;                 // filt channel
            float baseg = g_base[b * O_ + og], basef = g_base[b * O_ + of];
            float e0g = g_e0[b * O_ + og], e0f = g_e0[b * O_ + of];
            float e2g = g_e2[b * O_ + og], e2f = g_e2[b * O_ + of];
            float4 zq;
            float* zqp = (float*)&zq;
            #pragma unroll
            for (int li = 0; li < 4; li++) {
                int gl = l0 + r0 + li;
                float bg = baseg, bf = basef;
                if (gl == 0)      { bg -= e0g; bf -= e0f; }
                if (gl == L_ - 1) { bg -= e2g; bf -= e2f; }
                float ag, af;
                unpack2(acc2[q][li], ag, af);
                float yg = ag + bg;
                float yf = af + bf;
                float vg = v[0][q][li]; vg = vg + (yg - vg) / 1.2f;
                float vf = v[1][q][li]; vf = vf + (yf - vf) / 1.2f;
                bool sg = vg >= 0.5f;
                bool sf = vf >= 0.5f;
                v[0][q][li] = sg ? 0.f : vg;
                v[1][q][li] = sf ? 0.f : vf;
                zqp[li] = sf ? (sg ? ZB : ZA) : 0.f;
            }
            *(float4*)(zb + (size_t)og * L_ + l0 + r0) = zq;
        }
    }
}

// ---------------- output GEMM: [x+res ; skip], packed f32x2 ----------------
// grid: (L/64, 4 n-tiles, T*B), block 256
__global__ void __launch_bounds__(256, 2) k_out(const float* __restrict__ x,
                                                const float* __restrict__ b_skip,
                                                const float* __restrict__ b_res,
                                                float* __restrict__ out) {
    const int l0 = blockIdx.x * 64;
    const int nb = blockIdx.y * 128;
    const int t = blockIdx.z >> 4;
    const int b = blockIdx.z & 15;
    const int tid = threadIdx.x;
    const int tx = tid & 15;              // 4 rows (l)
    const int ty = tid >> 4;              // 8 cols (n) = 4 pairs

    __shared__ float zs[16][64];
    __shared__ float wn[16][128];

    u64 acc2[4][4];                       // 4 n-pairs x 4 l
    #pragma unroll
    for (int j = 0; j < 4; j++)
        #pragma unroll
        for (int li = 0; li < 4; li++) acc2[j][li] = 0ull;

    const float* zb = g_z + (size_t)((t * B_ + b) * C_) * L_;

    #pragma unroll 1
    for (int cc = 0; cc < C_; cc += 16) {
        {   // z tile: 1024 floats, one float4 per thread
            int ci = tid >> 4;
            int l4 = tid & 15;
            *(float4*)&zs[ci][l4 * 4] =
                *(const float4*)(zb + (cc + ci) * L_ + l0 + l4 * 4);
        }
        #pragma unroll
        for (int r = 0; r < 2; r++) {     // w tile: 2048 floats, 2 float4/thread
            int idx = tid + r * 256;      // 0..511
            int j4 = idx & 31;
            int ci = idx >> 5;
            *(float4*)&wn[ci][j4 * 4] =
                *(const float4*)(&g_wn[(cc + ci) * O_ + nb + j4 * 4]);
        }
        __syncthreads();

        #pragma unroll
        for (int ci = 0; ci < 16; ci++) {
            float4 zr = *(float4*)&zs[ci][tx * 4];
            u64 zz[4];
            zz[0] = pack2(zr.x, zr.x);
            zz[1] = pack2(zr.y, zr.y);
            zz[2] = pack2(zr.z, zr.z);
            zz[3] = pack2(zr.w, zr.w);
            #pragma unroll
            for (int j2 = 0; j2 < 4; j2++) {
                u64 w = *(const u64*)&wn[ci][ty * 8 + j2 * 2];
                #pragma unroll
                for (int li = 0; li < 4; li++)
                    acc2[j2][li] = fma2(w, zz[li], acc2[j2][li]);
            }
        }
        __syncthreads();
    }

    float acc[8][4];
    #pragma unroll
    for (int j2 = 0; j2 < 4; j2++)
        #pragma unroll
        for (int li = 0; li < 4; li++)
            unpack2(acc2[j2][li], acc[2 * j2][li], acc[2 * j2 + 1][li]);

    #pragma unroll
    for (int j = 0; j < 8; j++) {
        int n = nb + ty * 8 + j;
        bool isres = (n < C_);
        int o = isres ? n : (n - C_);
        size_t idx = ((size_t)(t * B_ + b) * C_ + o) * L_ + l0 + tx * 4;
        float bias = isres ? b_res[o] : b_skip[o];
        float4 r;
        if (isres) {
            float4 xv = *(const float4*)(x + idx);
            r.x = acc[j][0] + xv.x + bias;
            r.y = acc[j][1] + xv.y + bias;
            r.z = acc[j][2] + xv.z + bias;
            r.w = acc[j][3] + xv.w + bias;
            *(float4*)(out + idx) = r;
        } else {
            r.x = acc[j][0] + bias;
            r.y = acc[j][1] + bias;
            r.z = acc[j][2] + bias;
            r.w = acc[j][3] + bias;
            *(float4*)(out + TBCL_ + idx) = r;
        }
    }
}

extern "C" void kernel_launch(void* const* d_in, const int* in_sizes, int n_in,
                              void* d_out, int out_size) {
    const float* x      = (const float*)d_in[0];
    const int*   dstep  = (const int*)d_in[1];
    const float* w_emb1 = (const float*)d_in[2];
    const float* b_emb1 = (const float*)d_in[3];
    const float* w_emb2 = (const float*)d_in[4];
    const float* b_emb2 = (const float*)d_in[5];
    const float* w_proj = (const float*)d_in[6];
    const float* b_proj = (const float*)d_in[7];
    const float* w_conv = (const float*)d_in[8];
    const float* b_conv = (const float*)d_in[9];
    const float* w_skip = (const float*)d_in[10];
    const float* b_skip = (const float*)d_in[11];
    const float* w_res  = (const float*)d_in[12];
    const float* b_res  = (const float*)d_in[13];
    float* out = (float*)d_out;

    k_proj<<<B_, C_>>>(dstep, w_emb1, b_emb1, w_emb2, b_emb2, w_proj, b_proj);
    k_wtrans<<<(3 * C_ * O_ + 255) / 256, 256>>>(w_conv, w_skip, w_res);
    k_econv<<<dim3(B_, O_ / 128), 128>>>(b_conv);
    k_conv_lif<<<dim3(L_ / 64, 4, B_), 256>>>(x);
    k_out<<<dim3(L_ / 64, 4, T_ * B_), 256>>>(x, b_skip, b_res, out);
}

// round 5
// speedup vs baseline: 1.0782x; 1.0782x over previous
#include <cuda_runtime.h>
#include <cuda_fp16.h>
#include <math.h>
#include <stdint.h>

#define T_ 4
#define B_ 16
#define C_ 256
#define L_ 2048
#define O_ 512
#define TBCL_ (T_*B_*C_*L_)
#define ZA 0.38079708f
#define ZB 0.55676994f
#define DZ (ZB - ZA)

typedef unsigned long long u64;
typedef uint32_t u32;

__device__ __forceinline__ u64 pack2(float lo, float hi) {
    u64 d; asm("mov.b64 %0, {%1, %2};" : "=l"(d) : "f"(lo), "f"(hi)); return d;
}
__device__ __forceinline__ void unpack2(u64 v, float& lo, float& hi) {
    asm("mov.b64 {%0, %1}, %2;" : "=f"(lo), "=f"(hi) : "l"(v));
}
__device__ __forceinline__ u64 fma2(u64 a, u64 b, u64 c) {
    u64 d; asm("fma.rn.f32x2 %0, %1, %2, %3;" : "=l"(d) : "l"(a), "l"(b), "l"(c)); return d;
}
__device__ __forceinline__ u32 smem_u32(const void* p) {
    u32 a;
    asm("{ .reg .u64 t; cvta.to.shared.u64 t, %1; cvt.u32.u64 %0, t; }" : "=r"(a) : "l"(p));
    return a;
}
__device__ __forceinline__ void cp16(u32 dst, const void* src) {
    asm volatile("cp.async.cg.shared.global [%0], [%1], 16;" :: "r"(dst), "l"(src));
}
__device__ __forceinline__ void mma16816(float* c, u32 a0, u32 a1, u32 a2, u32 a3, u32 b0, u32 b1) {
    asm volatile("mma.sync.aligned.m16n8k16.row.col.f32.f16.f16.f32 "
                 "{%0,%1,%2,%3},{%4,%5,%6,%7},{%8,%9},{%0,%1,%2,%3};"
                 : "+f"(c[0]), "+f"(c[1]), "+f"(c[2]), "+f"(c[3])
                 : "r"(a0), "r"(a1), "r"(a2), "r"(a3), "r"(b0), "r"(b1));
}

// ---- device scratch ----
__device__ __half g_s[(size_t)T_*B_*L_*512];   // spikes [tb][l][512] = [u(256)|w(256)]
__device__ __half g_w2[512 * 1024];            // [n][1024]: k<512 hi split, k>=512 lo split
__device__ float g_proj[B_*C_];
__device__ float g_base[B_*O_];
__device__ float g_e0[B_*O_];
__device__ float g_e2[B_*O_];
__device__ float g_wc[3*C_*O_];                // [k][c][o]
__device__ float g_wn[C_*O_];                  // [c][n] n<256 res, else skip

// ---------------- prep kernels ----------------
__global__ void k_proj(const int* __restrict__ dstep,
                       const float* __restrict__ w1, const float* __restrict__ b1,
                       const float* __restrict__ w2, const float* __restrict__ b2,
                       const float* __restrict__ wp, const float* __restrict__ bp) {
    int b = blockIdx.x, c = threadIdx.x;
    __shared__ float h[C_], emb[C_];
    float ds = (float)dstep[b];
    float t1 = ds * w1[c] + b1[c];
    h[c] = t1 / (1.f + expf(-t1));
    __syncthreads();
    float e = b2[c];
    const float* w2r = w2 + c * C_;
    for (int j = 0; j < C_; j++) e += w2r[j] * h[j];
    __syncthreads();
    emb[c] = e;
    __syncthreads();
    float p = bp[c];
    const float* wpr = wp + c * C_;
    for (int j = 0; j < C_; j++) p += wpr[j] * emb[j];
    g_proj[b * C_ + c] = p;
}

__global__ void k_wtrans(const float* __restrict__ w_conv,
                         const float* __restrict__ w_skip,
                         const float* __restrict__ w_res) {
    int i = blockIdx.x * 256 + threadIdx.x;
    if (i < 3 * C_ * O_) {
        int o = i % O_, c = (i / O_) % C_, k = i / (O_ * C_);
        g_wc[i] = w_conv[(o * C_ + c) * 3 + k];
    }
    if (i < C_ * O_) {
        int n = i % O_, c = i / O_;
        g_wn[i] = (n < C_) ? w_res[n * C_ + c] : w_skip[(n - C_) * C_ + c];
    }
}

__global__ void k_w2build() {
    int i = blockIdx.x * 256 + threadIdx.x;   // 512*512
    int n = i >> 9, kk = i & 511;
    int c = kk & 255, part = kk >> 8;
    float base = (part ? DZ : ZA) * g_wn[c * O_ + n];
    __half h = __float2half(base);
    __half l = __float2half(base - __half2float(h));
    g_w2[n * 1024 + kk] = h;
    g_w2[n * 1024 + 512 + kk] = l;
}

__global__ void k_econv(const float* __restrict__ b_conv) {
    int b = blockIdx.x;
    int o = blockIdx.y * 128 + threadIdx.x;
    __shared__ float pr[C_];
    for (int i = threadIdx.x; i < C_; i += 128) pr[i] = g_proj[b * C_ + i];
    __syncthreads();
    float e0 = 0.f, e1 = 0.f, e2 = 0.f;
    for (int c = 0; c < C_; c++) {
        float p = pr[c];
        e0 += g_wc[(0 * C_ + c) * O_ + o] * p;
        e1 += g_wc[(1 * C_ + c) * O_ + o] * p;
        e2 += g_wc[(2 * C_ + c) * O_ + o] * p;
    }
    g_base[b * O_ + o] = e0 + e1 + e2 + b_conv[o];
    g_e0[b * O_ + o] = e0;
    g_e2[b * O_ + o] = e2;
}

// ---------------- conv1d + LIF -> binary spikes (f32x2 packed) ----------------
__global__ void __launch_bounds__(256, 2) k_conv_lif(const float* __restrict__ x) {
    const int l0 = blockIdx.x * 64;
    const int ot = blockIdx.y;
    const int b  = blockIdx.z;
    const int tid = threadIdx.x;
    const int tx = tid & 15, ty = tid >> 4;
    const int r0 = tx * 4;

    __shared__ float  xs[16][66];
    __shared__ float2 ws[16][3][64];
    __shared__ __half su[64][72];
    __shared__ __half sw[64][72];

    float v[2][4][4];
    #pragma unroll
    for (int h = 0; h < 2; h++)
        #pragma unroll
        for (int q = 0; q < 4; q++)
            #pragma unroll
            for (int li = 0; li < 4; li++) v[h][q][li] = 0.f;

    #pragma unroll 1
    for (int t = 0; t < T_; t++) {
        u64 acc2[4][4];
        #pragma unroll
        for (int q = 0; q < 4; q++)
            #pragma unroll
            for (int li = 0; li < 4; li++) acc2[q][li] = 0ull;

        const float* xb = x + (size_t)((t * B_ + b) * C_) * L_;

        #pragma unroll 1
        for (int cc = 0; cc < C_; cc += 16) {
            for (int i = tid; i < 16 * 66; i += 256) {
                int ci = i / 66, li = i % 66;
                int gl = l0 - 1 + li;
                float val = 0.f;
                if (gl >= 0 && gl < L_) val = xb[(cc + ci) * L_ + gl];
                xs[ci][li] = val;
            }
            for (int i = tid; i < 3072; i += 256) {
                int p = i & 63, k = (i >> 6) % 3, ci = i / 192;
                int og = ot * 64 + p;
                const float* wr = &g_wc[(k * C_ + cc + ci) * O_];
                ws[ci][k][p] = make_float2(wr[og], wr[og + 256]);
            }
            __syncthreads();
            #pragma unroll
            for (int ci = 0; ci < 16; ci++) {
                u64 xx[6];
                #pragma unroll
                for (int s = 0; s < 6; s++) {
                    float xv = xs[ci][r0 + s];
                    xx[s] = pack2(xv, xv);
                }
                #pragma unroll
                for (int q = 0; q < 4; q++) {
                    int cq = ty * 4 + q;
                    u64 w0 = *(const u64*)&ws[ci][0][cq];
                    u64 w1 = *(const u64*)&ws[ci][1][cq];
                    u64 w2 = *(const u64*)&ws[ci][2][cq];
                    #pragma unroll
                    for (int li = 0; li < 4; li++) {
                        acc2[q][li] = fma2(w0, xx[li],     acc2[q][li]);
                        acc2[q][li] = fma2(w1, xx[li + 1], acc2[q][li]);
                        acc2[q][li] = fma2(w2, xx[li + 2], acc2[q][li]);
                    }
                }
            }
            __syncthreads();
        }

        // LIF + spike staging
        const __half one = __float2half(1.f), zero = __float2half(0.f);
        #pragma unroll
        for (int q = 0; q < 4; q++) {
            int og = ot * 64 + ty * 4 + q;
            int of = og + 256;
            float baseg = g_base[b * O_ + og], basef = g_base[b * O_ + of];
            float e0g = g_e0[b * O_ + og], e0f = g_e0[b * O_ + of];
            float e2g = g_e2[b * O_ + og], e2f = g_e2[b * O_ + of];
            #pragma unroll
            for (int li = 0; li < 4; li++) {
                int gl = l0 + r0 + li;
                float bg = baseg, bf = basef;
                if (gl == 0)      { bg -= e0g; bf -= e0f; }
                if (gl == L_ - 1) { bg -= e2g; bf -= e2f; }
                float ag, af;
                unpack2(acc2[q][li], ag, af);
                float yg = ag + bg, yf = af + bf;
                float vg = v[0][q][li]; vg = vg + (yg - vg) / 1.2f;
                float vf = v[1][q][li]; vf = vf + (yf - vf) / 1.2f;
                bool sg = vg >= 0.5f, sf = vf >= 0.5f;
                v[0][q][li] = sg ? 0.f : vg;
                v[1][q][li] = sf ? 0.f : vf;
                su[r0 + li][ty * 4 + q] = sf ? one : zero;          // u (coeff ZA)
                sw[r0 + li][ty * 4 + q] = (sf && sg) ? one : zero;  // w (coeff DZ)
            }
        }
        __syncthreads();
        {   // coalesced spike store: row = l, 512 halves [u|w]
            int row = tid >> 2, seg = tid & 3;
            __half* dst = g_s + ((size_t)(t * B_ + b) * L_ + l0 + row) * 512;
            uint4 a0 = *(uint4*)&su[row][seg * 16];
            uint4 a1 = *(uint4*)&su[row][seg * 16 + 8];
            uint4 b0 = *(uint4*)&sw[row][seg * 16];
            uint4 b1 = *(uint4*)&sw[row][seg * 16 + 8];
            *(uint4*)(dst + ot * 64 + seg * 16)           = a0;
            *(uint4*)(dst + ot * 64 + seg * 16 + 8)       = a1;
            *(uint4*)(dst + 256 + ot * 64 + seg * 16)     = b0;
            *(uint4*)(dst + 256 + ot * 64 + seg * 16 + 8) = b1;
        }
        __syncthreads();
    }
}

// ---------------- output GEMM via mma.sync (HMMA) ----------------
// out[n][l] = (Whi+Wlo)[n][k] * S[l][k]^T ; fused x+bias epilogue.
// grid (16 lt, 4 nt, 64 tb), 256 threads (8 warps: 4 n-groups x 2 l-groups)
// smem: S[2][128][40] @0, Whi[2][128][40] @20480B, Wlo @40960B; total 61440B
#define SMEM_OUT 61440
#define RS 40   // padded row stride in halves

__global__ void __launch_bounds__(256) k_out_mma(const float* __restrict__ x,
                                                 const float* __restrict__ b_skip,
                                                 const float* __restrict__ b_res,
                                                 float* __restrict__ out) {
    extern __shared__ __half sm[];
    const int lt = blockIdx.x, nt = blockIdx.y, tb = blockIdx.z;
    const int tid = threadIdx.x;
    const int wid = tid >> 5, lane = tid & 31;
    const int wn = wid >> 1;          // n-group 0..3  -> n0w = wn*32
    const int wl = wid & 1;           // l-group 0..1  -> l0w = wl*64
    const u32 sb = smem_u32(sm);

    const __half* gS = g_s + ((size_t)tb * L_ + lt * 128) * 512;
    const __half* gW = g_w2 + (size_t)(nt * 128) * 1024;

    float acc[2][8][4];
    #pragma unroll
    for (int m = 0; m < 2; m++)
        #pragma unroll
        for (int j = 0; j < 8; j++)
            #pragma unroll
            for (int e = 0; e < 4; e++) acc[m][j][e] = 0.f;

    // chunk loader: stage s, k0 = c*32
    auto load_chunk = [&](int c) {
        int s = c & 1;
        int k0 = c * 32;
        u32 sS = sb + s * 10240;
        u32 sH = sb + 20480 + s * 10240;
        u32 sL = sb + 40960 + s * 10240;
        #pragma unroll
        for (int j = 0; j < 2; j++) {
            int v = tid + j * 256;            // 0..511
            int r = v >> 2, c16 = v & 3;
            u32 doff = (u32)(r * RS + c16 * 8) * 2;
            cp16(sS + doff, gS + (size_t)r * 512 + k0 + c16 * 8);
            cp16(sH + doff, gW + (size_t)r * 1024 + k0 + c16 * 8);
            cp16(sL + doff, gW + (size_t)r * 1024 + 512 + k0 + c16 * 8);
        }
        asm volatile("cp.async.commit_group;" ::: "memory");
    };

    load_chunk(0);
    load_chunk(1);

    const int r4 = lane >> 2, c2 = 2 * (lane & 3);

    #pragma unroll 1
    for (int c = 0; c < 16; c++) {
        if (c + 2 < 16) asm volatile("cp.async.wait_group 1;" ::: "memory");
        else            asm volatile("cp.async.wait_group 0;" ::: "memory");
        __syncthreads();
        int s = c & 1;
        const __half* S  = sm + s * 5120;
        const __half* WH = sm + 10240 + s * 5120;
        const __half* WL = sm + 20480 + s * 5120;

        #pragma unroll
        for (int ks = 0; ks < 2; ks++) {
            int k0s = ks * 16;
            // B frags: spikes, 8 l-subtiles
            u32 bs0[8], bs1[8];
            #pragma unroll
            for (int j = 0; j < 8; j++) {
                int l = wl * 64 + j * 8 + r4;
                const __half* p = S + l * RS + k0s + c2;
                bs0[j] = *(const u32*)p;
                bs1[j] = *(const u32*)(p + 8);
            }
            // A frags: weights hi/lo, 2 m-subtiles each
            #pragma unroll
            for (int m = 0; m < 2; m++) {
                int row = wn * 32 + m * 16 + r4;
                #pragma unroll
                for (int sp = 0; sp < 2; sp++) {
                    const __half* W = sp ? WL : WH;
                    const __half* p = W + row * RS + k0s + c2;
                    u32 a0 = *(const u32*)p;
                    u32 a1 = *(const u32*)(p + 8 * RS);
                    u32 a2 = *(const u32*)(p + 8);
                    u32 a3 = *(const u32*)(p + 8 * RS + 8);
                    #pragma unroll
                    for (int j = 0; j < 8; j++)
                        mma16816(acc[m][j], a0, a1, a2, a3, bs0[j], bs1[j]);
                }
            }
        }
        __syncthreads();
        if (c + 2 < 16) load_chunk(c + 2);
    }

    // epilogue: C rows = n, cols = l; c0,c1 at (r4, c2..c2+1), c2,c3 at (r4+8, ..)
    size_t base_tb = (size_t)tb * C_ * L_;
    #pragma unroll
    for (int m = 0; m < 2; m++) {
        #pragma unroll
        for (int j = 0; j < 8; j++) {
            int lg = lt * 128 + wl * 64 + j * 8 + c2;
            #pragma unroll
            for (int half = 0; half < 2; half++) {
                int ng = nt * 128 + wn * 32 + m * 16 + r4 + half * 8;
                float v0 = acc[m][j][half * 2], v1 = acc[m][j][half * 2 + 1];
                if (ng < 256) {
                    size_t idx = base_tb + (size_t)ng * L_ + lg;
                    float bias = b_res[ng];
                    float2 xv = *(const float2*)(x + idx);
                    float2 r = make_float2(v0 + xv.x + bias, v1 + xv.y + bias);
                    *(float2*)(out + idx) = r;
                } else {
                    int o = ng - 256;
                    size_t idx = base_tb + (size_t)o * L_ + lg;
                    float bias = b_skip[o];
                    float2 r = make_float2(v0 + bias, v1 + bias);
                    *(float2*)(out + TBCL_ + idx) = r;
                }
            }
        }
    }
}

extern "C" void kernel_launch(void* const* d_in, const int* in_sizes, int n_in,
                              void* d_out, int out_size) {
    const float* x      = (const float*)d_in[0];
    const int*   dstep  = (const int*)d_in[1];
    const float* w_emb1 = (const float*)d_in[2];
    const float* b_emb1 = (const float*)d_in[3];
    const float* w_emb2 = (const float*)d_in[4];
    const float* b_emb2 = (const float*)d_in[5];
    const float* w_proj = (const float*)d_in[6];
    const float* b_proj = (const float*)d_in[7];
    const float* w_conv = (const float*)d_in[8];
    const float* b_conv = (const float*)d_in[9];
    const float* w_skip = (const float*)d_in[10];
    const float* b_skip = (const float*)d_in[11];
    const float* w_res  = (const float*)d_in[12];
    const float* b_res  = (const float*)d_in[13];
    float* out = (float*)d_out;

    static int attr_set = 0;
    if (!attr_set) {
        cudaFuncSetAttribute(k_out_mma, cudaFuncAttributeMaxDynamicSharedMemorySize, SMEM_OUT);
        attr_set = 1;
    }

    k_proj<<<B_, C_>>>(dstep, w_emb1, b_emb1, w_emb2, b_emb2, w_proj, b_proj);
    k_wtrans<<<(3 * C_ * O_ + 255) / 256, 256>>>(w_conv, w_skip, w_res);
    k_w2build<<<512 * 512 / 256, 256>>>();
    k_econv<<<dim3(B_, O_ / 128), 128>>>(b_conv);
    k_conv_lif<<<dim3(L_ / 64, 4, B_), 256>>>(x);
    k_out_mma<<<dim3(16, 4, 64), 256, SMEM_OUT>>>(x, b_skip, b_res, out);
}

// round 6
// speedup vs baseline: 1.1190x; 1.0379x over previous
#include <cuda_runtime.h>
#include <cuda_fp16.h>
#include <math.h>
#include <stdint.h>

#define T_ 4
#define B_ 16
#define C_ 256
#define L_ 2048
#define O_ 512
#define TBCL_ (T_*B_*C_*L_)
#define ZA 0.38079708f
#define ZB 0.55676994f
#define DZ (ZB - ZA)
#define XS 16.0f
#define WSC 128.0f
#define INV_SC (1.0f/2048.0f)

typedef unsigned long long u64;
typedef uint32_t u32;

__device__ __forceinline__ u32 smem_u32(const void* p) {
    u32 a;
    asm("{ .reg .u64 t; cvta.to.shared.u64 t, %1; cvt.u32.u64 %0, t; }" : "=r"(a) : "l"(p));
    return a;
}
__device__ __forceinline__ void cp16(u32 dst, const void* src) {
    asm volatile("cp.async.cg.shared.global [%0], [%1], 16;" :: "r"(dst), "l"(src));
}
__device__ __forceinline__ void mma16816(float* c, u32 a0, u32 a1, u32 a2, u32 a3, u32 b0, u32 b1) {
    asm volatile("mma.sync.aligned.m16n8k16.row.col.f32.f16.f16.f32 "
                 "{%0,%1,%2,%3},{%4,%5,%6,%7},{%8,%9},{%0,%1,%2,%3};"
                 : "+f"(c[0]), "+f"(c[1]), "+f"(c[2]), "+f"(c[3])
                 : "r"(a0), "r"(a1), "r"(a2), "r"(a3), "r"(b0), "r"(b1));
}

// ---- device scratch ----
__device__ __half g_s[(size_t)T_*B_*L_*512];   // spikes [tb][l][512] = [u(256)|w(256)]
__device__ __half g_w2[512 * 1024];            // out-GEMM weights [n][1024] hi|lo
__device__ __half g_wcs[9 * 512 * 256];        // conv w splits [split][shift][o][c], x128
__device__ float g_proj[B_*C_];
__device__ float g_base[B_*O_];
__device__ float g_e0[B_*O_];
__device__ float g_e2[B_*O_];
__device__ float g_wc[3*C_*O_];                // [k][c][o] fp32 (for k_econv)
__device__ float g_wn[C_*O_];                  // [c][n] n<256 res, else skip

// ---------------- prep kernels ----------------
__global__ void k_proj(const int* __restrict__ dstep,
                       const float* __restrict__ w1, const float* __restrict__ b1,
                       const float* __restrict__ w2, const float* __restrict__ b2,
                       const float* __restrict__ wp, const float* __restrict__ bp) {
    int b = blockIdx.x, c = threadIdx.x;
    __shared__ float h[C_], emb[C_];
    float ds = (float)dstep[b];
    float t1 = ds * w1[c] + b1[c];
    h[c] = t1 / (1.f + expf(-t1));
    __syncthreads();
    float e = b2[c];
    const float* w2r = w2 + c * C_;
    for (int j = 0; j < C_; j++) e += w2r[j] * h[j];
    __syncthreads();
    emb[c] = e;
    __syncthreads();
    float p = bp[c];
    const float* wpr = wp + c * C_;
    for (int j = 0; j < C_; j++) p += wpr[j] * emb[j];
    g_proj[b * C_ + c] = p;
}

__global__ void k_wtrans(const float* __restrict__ w_conv,
                         const float* __restrict__ w_skip,
                         const float* __restrict__ w_res) {
    int i = blockIdx.x * 256 + threadIdx.x;
    if (i < 3 * C_ * O_) {
        int o = i % O_, c = (i / O_) % C_, k = i / (O_ * C_);
        g_wc[i] = w_conv[(o * C_ + c) * 3 + k];
    }
    if (i < C_ * O_) {
        int n = i % O_, c = i / O_;
        g_wn[i] = (n < C_) ? w_res[n * C_ + c] : w_skip[(n - C_) * C_ + c];
    }
}

__global__ void k_w2build() {
    int i = blockIdx.x * 256 + threadIdx.x;
    int n = i >> 9, kk = i & 511;
    int c = kk & 255, part = kk >> 8;
    float base = (part ? DZ : ZA) * g_wn[c * O_ + n];
    __half h = __float2half(base);
    __half l = __float2half(base - __half2float(h));
    g_w2[n * 1024 + kk] = h;
    g_w2[n * 1024 + 512 + kk] = l;
}

__global__ void k_wsplit(const float* __restrict__ w_conv) {
    int i = blockIdx.x * 256 + threadIdx.x;    // 512*256 (o,c)
    int o = i >> 8, c = i & 255;
    #pragma unroll
    for (int k = 0; k < 3; k++) {
        float w = w_conv[(o * C_ + c) * 3 + k] * WSC;
        __half h1 = __float2half_rn(w);
        float r1 = w - __half2float(h1);
        __half h2 = __float2half_rn(r1);
        float r2 = r1 - __half2float(h2);
        __half h3 = __float2half_rn(r2);
        size_t base = ((size_t)k * 512 + o) * 256 + c;
        g_wcs[0 * 393216 + base] = h1;
        g_wcs[1 * 393216 + base] = h2;
        g_wcs[2 * 393216 + base] = h3;
    }
}

__global__ void k_econv(const float* __restrict__ b_conv) {
    int b = blockIdx.x;
    int o = blockIdx.y * 128 + threadIdx.x;
    __shared__ float pr[C_];
    for (int i = threadIdx.x; i < C_; i += 128) pr[i] = g_proj[b * C_ + i];
    __syncthreads();
    float e0 = 0.f, e1 = 0.f, e2 = 0.f;
    #pragma unroll 4
    for (int c = 0; c < C_; c++) {
        float p = pr[c];
        e0 += g_wc[(0 * C_ + c) * O_ + o] * p;
        e1 += g_wc[(1 * C_ + c) * O_ + o] * p;
        e2 += g_wc[(2 * C_ + c) * O_ + o] * p;
    }
    g_base[b * O_ + o] = e0 + e1 + e2 + b_conv[o];
    g_e0[b * O_ + o] = e0;
    g_e2[b * O_ + o] = e2;
}

// ---------------- conv1d + LIF via HMMA (fp16x3 exact split) ----------------
// grid (32 lt, 4 ot, 16 b), 256 threads.
// smem/stage: ws[9 q][128 m][24 halves] = 55296B ; xs[3 sp][66 l][18 c] = 7128B
#define WS_SZ 55296
#define CSTAGE 62464
#define CONV_SMEM (2*CSTAGE + 2*9216)

__global__ void __launch_bounds__(256, 1) k_conv_mma(const float* __restrict__ x) {
    extern __shared__ char sm[];
    const u32 sb = smem_u32(sm);
    const int lt = blockIdx.x, ot = blockIdx.y, b = blockIdx.z;
    const int l0 = lt * 64;
    const int tid = threadIdx.x, wid = tid >> 5, lane = tid & 31;
    const int wn = wid >> 1, wl = wid & 1;
    const int r4 = lane >> 2, c2 = (lane & 3) * 2;

    __half* su  = (__half*)(sm + 2 * CSTAGE);
    __half* sw_ = (__half*)(sm + 2 * CSTAGE + 9216);

    auto load_step = [&](int step) {
        int t = step >> 4, cc = (step & 15) << 4, s = step & 1;
        u32 wsb = sb + s * CSTAGE;
        // weights: 2304 cp16 (9 per thread)
        #pragma unroll
        for (int j = 0; j < 9; j++) {
            int idx = tid + j * 256;
            int c16 = idx & 1;
            int m = (idx >> 1) & 127;
            int q = idx >> 8;              // = sh*3 + sp
            int sh = q / 3, sp = q % 3;
            int o = (m < 64) ? (ot * 64 + m) : (256 + ot * 64 + m - 64);
            const __half* src = g_wcs + (((size_t)(sp * 3 + sh) * 512 + o) << 8) + cc + c16 * 8;
            cp16(wsb + (u32)((q * 128 + m) * 48 + c16 * 16), src);
        }
        asm volatile("cp.async.commit_group;" ::: "memory");
        // x tile: fp32 load -> 3-way fp16 split, transposed [l][c]
        __half* xs = (__half*)(sm + s * CSTAGE + WS_SZ);
        int c = tid >> 4, lb = tid & 15;
        const float* xr = x + ((size_t)((t * B_ + b) * C_) + cc + c) * L_;
        #pragma unroll
        for (int k = 0; k < 5; k++) {
            int li = lb + k * 16;
            if (li < 66) {
                int gl = l0 - 1 + li;
                float v = 0.f;
                if (gl >= 0 && gl < L_) v = xr[gl] * XS;
                __half h1 = __float2half_rn(v);
                float r1 = v - __half2float(h1);
                __half h2 = __float2half_rn(r1);
                float r2 = r1 - __half2float(h2);
                __half h3 = __float2half_rn(r2);
                xs[(0 * 66 + li) * 18 + c] = h1;
                xs[(1 * 66 + li) * 18 + c] = h2;
                xs[(2 * 66 + li) * 18 + c] = h3;
            }
        }
    };

    float acc[2][4][4];
    float v[2][2][8];
    #pragma unroll
    for (int m = 0; m < 2; m++)
        #pragma unroll
        for (int j = 0; j < 4; j++)
            #pragma unroll
            for (int e = 0; e < 4; e++) acc[m][j][e] = 0.f;
    #pragma unroll
    for (int g = 0; g < 2; g++)
        #pragma unroll
        for (int h = 0; h < 2; h++)
            #pragma unroll
            for (int e = 0; e < 8; e++) v[g][h][e] = 0.f;

    load_step(0);
    load_step(1);

    const __half one = __float2half(1.f), zero = __float2half(0.f);

    #pragma unroll 1
    for (int step = 0; step < 64; step++) {
        if (step < 62) asm volatile("cp.async.wait_group 1;" ::: "memory");
        else           asm volatile("cp.async.wait_group 0;" ::: "memory");
        __syncthreads();
        int s = step & 1;
        const char* wsb = sm + s * CSTAGE;
        const __half* xs = (const __half*)(sm + s * CSTAGE + WS_SZ);

        #pragma unroll
        for (int sh = 0; sh < 3; sh++) {
            u32 bf0[3][4], bf1[3][4];
            #pragma unroll
            for (int sp = 0; sp < 3; sp++)
                #pragma unroll
                for (int j = 0; j < 4; j++) {
                    const __half* p = xs + (sp * 66 + wl * 32 + j * 8 + r4 + sh) * 18 + c2;
                    bf0[sp][j] = *(const u32*)p;
                    bf1[sp][j] = *(const u32*)(p + 8);
                }
            u32 a[3][2][4];
            #pragma unroll
            for (int sp = 0; sp < 3; sp++)
                #pragma unroll
                for (int m = 0; m < 2; m++) {
                    const __half* p = (const __half*)(wsb + ((sh * 3 + sp) * 128 + m * 64 + wn * 16 + r4) * 48) + c2;
                    a[sp][m][0] = *(const u32*)p;
                    a[sp][m][1] = *(const u32*)(p + 8 * 24);
                    a[sp][m][2] = *(const u32*)(p + 8);
                    a[sp][m][3] = *(const u32*)(p + 8 * 24 + 8);
                }
            #pragma unroll
            for (int m = 0; m < 2; m++)
                #pragma unroll
                for (int j = 0; j < 4; j++) {
                    #define TRM(xi, wi) mma16816(acc[m][j], a[wi][m][0], a[wi][m][1], a[wi][m][2], a[wi][m][3], bf0[xi][j], bf1[xi][j])
                    TRM(0, 0); TRM(0, 1); TRM(1, 0); TRM(0, 2); TRM(1, 1); TRM(2, 0);
                    #undef TRM
                }
        }
        __syncthreads();
        if (step + 2 < 64) load_step(step + 2);

        if ((step & 15) == 15) {   // epilogue for this t
            int t = step >> 4;
            int chb = ot * 64 + wn * 16 + r4;
            #pragma unroll
            for (int h = 0; h < 2; h++) {
                int cg = chb + h * 8;
                int cf = cg + 256;
                float bg0 = g_base[b * O_ + cg], bf0v = g_base[b * O_ + cf];
                float e0g = g_e0[b * O_ + cg], e0f = g_e0[b * O_ + cf];
                float e2g = g_e2[b * O_ + cg], e2f = g_e2[b * O_ + cf];
                #pragma unroll
                for (int j = 0; j < 4; j++)
                    #pragma unroll
                    for (int e = 0; e < 2; e++) {
                        int ll = wl * 32 + j * 8 + c2 + e;
                        int gl = l0 + ll;
                        float bg = bg0, bfv = bf0v;
                        if (gl == 0)      { bg -= e0g; bfv -= e0f; }
                        if (gl == L_ - 1) { bg -= e2g; bfv -= e2f; }
                        float yg = acc[0][j][h * 2 + e] * INV_SC + bg;
                        float yf = acc[1][j][h * 2 + e] * INV_SC + bfv;
                        int vi = j * 2 + e;
                        float vg = v[0][h][vi]; vg = vg + (yg - vg) / 1.2f;
                        float vf = v[1][h][vi]; vf = vf + (yf - vf) / 1.2f;
                        bool sg = vg >= 0.5f, sf = vf >= 0.5f;
                        v[0][h][vi] = sg ? 0.f : vg;
                        v[1][h][vi] = sf ? 0.f : vf;
                        su[ll * 72 + wn * 16 + r4 + h * 8] = sf ? one : zero;
                        sw_[ll * 72 + wn * 16 + r4 + h * 8] = (sf && sg) ? one : zero;
                    }
            }
            #pragma unroll
            for (int m = 0; m < 2; m++)
                #pragma unroll
                for (int j = 0; j < 4; j++)
                    #pragma unroll
                    for (int e = 0; e < 4; e++) acc[m][j][e] = 0.f;
            __syncthreads();
            {
                int row = tid >> 2, seg = tid & 3;
                __half* dst = g_s + ((size_t)(t * B_ + b) * L_ + l0 + row) * 512;
                uint4 a0 = *(uint4*)&su[row * 72 + seg * 16];
                uint4 a1 = *(uint4*)&su[row * 72 + seg * 16 + 8];
                uint4 b0 = *(uint4*)&sw_[row * 72 + seg * 16];
                uint4 b1 = *(uint4*)&sw_[row * 72 + seg * 16 + 8];
                *(uint4*)(dst + ot * 64 + seg * 16)           = a0;
                *(uint4*)(dst + ot * 64 + seg * 16 + 8)       = a1;
                *(uint4*)(dst + 256 + ot * 64 + seg * 16)     = b0;
                *(uint4*)(dst + 256 + ot * 64 + seg * 16 + 8) = b1;
            }
            __syncthreads();
        }
    }
}

// ---------------- output GEMM via mma.sync (HMMA), unchanged from R5 ----------------
#define SMEM_OUT 61440
#define RS 40

__global__ void __launch_bounds__(256) k_out_mma(const float* __restrict__ x,
                                                 const float* __restrict__ b_skip,
                                                 const float* __restrict__ b_res,
                                                 float* __restrict__ out) {
    extern __shared__ __half smo[];
    const int lt = blockIdx.x, nt = blockIdx.y, tb = blockIdx.z;
    const int tid = threadIdx.x;
    const int wid = tid >> 5, lane = tid & 31;
    const int wn = wid >> 1;
    const int wl = wid & 1;
    const u32 sb = smem_u32(smo);

    const __half* gS = g_s + ((size_t)tb * L_ + lt * 128) * 512;
    const __half* gW = g_w2 + (size_t)(nt * 128) * 1024;

    float acc[2][8][4];
    #pragma unroll
    for (int m = 0; m < 2; m++)
        #pragma unroll
        for (int j = 0; j < 8; j++)
            #pragma unroll
            for (int e = 0; e < 4; e++) acc[m][j][e] = 0.f;

    auto load_chunk = [&](int c) {
        int s = c & 1;
        int k0 = c * 32;
        u32 sS = sb + s * 10240;
        u32 sH = sb + 20480 + s * 10240;
        u32 sL = sb + 40960 + s * 10240;
        #pragma unroll
        for (int j = 0; j < 2; j++) {
            int vv = tid + j * 256;
            int r = vv >> 2, c16 = vv & 3;
            u32 doff = (u32)(r * RS + c16 * 8) * 2;
            cp16(sS + doff, gS + (size_t)r * 512 + k0 + c16 * 8);
            cp16(sH + doff, gW + (size_t)r * 1024 + k0 + c16 * 8);
            cp16(sL + doff, gW + (size_t)r * 1024 + 512 + k0 + c16 * 8);
        }
        asm volatile("cp.async.commit_group;" ::: "memory");
    };

    load_chunk(0);
    load_chunk(1);

    const int r4 = lane >> 2, c2 = 2 * (lane & 3);

    #pragma unroll 1
    for (int c = 0; c < 16; c++) {
        if (c + 2 < 16) asm volatile("cp.async.wait_group 1;" ::: "memory");
        else            asm volatile("cp.async.wait_group 0;" ::: "memory");
        __syncthreads();
        int s = c & 1;
        const __half* S  = smo + s * 5120;
        const __half* WH = smo + 10240 + s * 5120;
        const __half* WL = smo + 20480 + s * 5120;

        #pragma unroll
        for (int ks = 0; ks < 2; ks++) {
            int k0s = ks * 16;
            u32 bs0[8], bs1[8];
            #pragma unroll
            for (int j = 0; j < 8; j++) {
                int l = wl * 64 + j * 8 + r4;
                const __half* p = S + l * RS + k0s + c2;
                bs0[j] = *(const u32*)p;
                bs1[j] = *(const u32*)(p + 8);
            }
            #pragma unroll
            for (int m = 0; m < 2; m++) {
                int row = wn * 32 + m * 16 + r4;
                #pragma unroll
                for (int sp = 0; sp < 2; sp++) {
                    const __half* W = sp ? WL : WH;
                    const __half* p = W + row * RS + k0s + c2;
                    u32 a0 = *(const u32*)p;
                    u32 a1 = *(const u32*)(p + 8 * RS);
                    u32 a2 = *(const u32*)(p + 8);
                    u32 a3 = *(const u32*)(p + 8 * RS + 8);
                    #pragma unroll
                    for (int j = 0; j < 8; j++)
                        mma16816(acc[m][j], a0, a1, a2, a3, bs0[j], bs1[j]);
                }
            }
        }
        __syncthreads();
        if (c + 2 < 16) load_chunk(c + 2);
    }

    size_t base_tb = (size_t)tb * C_ * L_;
    #pragma unroll
    for (int m = 0; m < 2; m++) {
        #pragma unroll
        for (int j = 0; j < 8; j++) {
            int lg = lt * 128 + wl * 64 + j * 8 + c2;
            #pragma unroll
            for (int half = 0; half < 2; half++) {
                int ng = nt * 128 + wn * 32 + m * 16 + r4 + half * 8;
                float v0 = acc[m][j][half * 2], v1 = acc[m][j][half * 2 + 1];
                if (ng < 256) {
                    size_t idx = base_tb + (size_t)ng * L_ + lg;
                    float bias = b_res[ng];
                    float2 xv = *(const float2*)(x + idx);
                    *(float2*)(out + idx) = make_float2(v0 + xv.x + bias, v1 + xv.y + bias);
                } else {
                    int o = ng - 256;
                    size_t idx = base_tb + (size_t)o * L_ + lg;
                    float bias = b_skip[o];
                    *(float2*)(out + TBCL_ + idx) = make_float2(v0 + bias, v1 + bias);
                }
            }
        }
    }
}

extern "C" void kernel_launch(void* const* d_in, const int* in_sizes, int n_in,
                              void* d_out, int out_size) {
    const float* x      = (const float*)d_in[0];
    const int*   dstep  = (const int*)d_in[1];
    const float* w_emb1 = (const float*)d_in[2];
    const float* b_emb1 = (const float*)d_in[3];
    const float* w_emb2 = (const float*)d_in[4];
    const float* b_emb2 = (const float*)d_in[5];
    const float* w_proj = (const float*)d_in[6];
    const float* b_proj = (const float*)d_in[7];
    const float* w_conv = (const float*)d_in[8];
    const float* b_conv = (const float*)d_in[9];
    const float* w_skip = (const float*)d_in[10];
    const float* b_skip = (const float*)d_in[11];
    const float* w_res  = (const float*)d_in[12];
    const float* b_res  = (const float*)d_in[13];
    float* out = (float*)d_out;

    static int attr_set = 0;
    if (!attr_set) {
        cudaFuncSetAttribute(k_out_mma, cudaFuncAttributeMaxDynamicSharedMemorySize, SMEM_OUT);
        cudaFuncSetAttribute(k_conv_mma, cudaFuncAttributeMaxDynamicSharedMemorySize, CONV_SMEM);
        attr_set = 1;
    }

    k_proj<<<B_, C_>>>(dstep, w_emb1, b_emb1, w_emb2, b_emb2, w_proj, b_proj);
    k_wtrans<<<(3 * C_ * O_ + 255) / 256, 256>>>(w_conv, w_skip, w_res);
    k_w2build<<<512 * 512 / 256, 256>>>();
    k_wsplit<<<512 * 256 / 256, 256>>>(w_conv);
    k_econv<<<dim3(B_, O_ / 128), 128>>>(b_conv);
    k_conv_mma<<<dim3(32, 4, 16), 256, CONV_SMEM>>>(x);
    k_out_mma<<<dim3(16, 4, 64), 256, SMEM_OUT>>>(x, b_skip, b_res, out);
}

// round 9
// speedup vs baseline: 1.7843x; 1.5945x over previous
#include <cuda_runtime.h>
#include <cuda_fp16.h>
#include <math.h>
#include <stdint.h>

#define T_ 4
#define B_ 16
#define C_ 256
#define L_ 2048
#define O_ 512
#define TBCL_ (T_*B_*C_*L_)
#define ZA 0.38079708f
#define ZB 0.55676994f
#define DZ (ZB - ZA)
#define XS 16.0f
#define WSC 128.0f
#define INV_SC (1.0f/2048.0f)

typedef unsigned long long u64;
typedef uint32_t u32;

__device__ __forceinline__ u32 smem_u32(const void* p) {
    u32 a;
    asm("{ .reg .u64 t; cvta.to.shared.u64 t, %1; cvt.u32.u64 %0, t; }" : "=r"(a) : "l"(p));
    return a;
}
__device__ __forceinline__ void cp16(u32 dst, const void* src) {
    asm volatile("cp.async.cg.shared.global [%0], [%1], 16;" :: "r"(dst), "l"(src));
}
__device__ __forceinline__ void mma16816(float* c, u32 a0, u32 a1, u32 a2, u32 a3, u32 b0, u32 b1) {
    asm volatile("mma.sync.aligned.m16n8k16.row.col.f32.f16.f16.f32 "
                 "{%0,%1,%2,%3},{%4,%5,%6,%7},{%8,%9},{%0,%1,%2,%3};"
                 : "+f"(c[0]), "+f"(c[1]), "+f"(c[2]), "+f"(c[3])
                 : "r"(a0), "r"(a1), "r"(a2), "r"(a3), "r"(b0), "r"(b1));
}

// ---- device scratch ----
__device__ __half g_s[(size_t)T_*B_*L_*512];   // spikes [tb][l][512] = [u(256)|w(256)]
__device__ __half g_w2[512 * 1024];            // out-GEMM weights [n][1024] hi|lo
__device__ __half g_wcs[6 * 512 * 256];        // conv w splits [sp][sh][o][c], x128
__device__ float g_proj[B_*C_];
__device__ float g_base[B_*O_];
__device__ float g_e0[B_*O_];
__device__ float g_e2[B_*O_];
__device__ float g_wc[3*C_*O_];                // [k][c][o] fp32 (for k_econv)
__device__ float g_wn[C_*O_];                  // [c][n] n<256 res, else skip

// ---------------- prep kernels ----------------
__global__ void k_proj(const int* __restrict__ dstep,
                       const float* __restrict__ w1, const float* __restrict__ b1,
                       const float* __restrict__ w2, const float* __restrict__ b2,
                       const float* __restrict__ wp, const float* __restrict__ bp) {
    int b = blockIdx.x, c = threadIdx.x;
    __shared__ float h[C_], emb[C_];
    float ds = (float)dstep[b];
    float t1 = ds * w1[c] + b1[c];
    h[c] = t1 / (1.f + expf(-t1));
    __syncthreads();
    float e = b2[c];
    const float* w2r = w2 + c * C_;
    for (int j = 0; j < C_; j++) e += w2r[j] * h[j];
    __syncthreads();
    emb[c] = e;
    __syncthreads();
    float p = bp[c];
    const float* wpr = wp + c * C_;
    for (int j = 0; j < C_; j++) p += wpr[j] * emb[j];
    g_proj[b * C_ + c] = p;
}

__global__ void k_wtrans(const float* __restrict__ w_conv,
                         const float* __restrict__ w_skip,
                         const float* __restrict__ w_res) {
    int i = blockIdx.x * 256 + threadIdx.x;
    if (i < 3 * C_ * O_) {
        int o = i % O_, c = (i / O_) % C_, k = i / (O_ * C_);
        g_wc[i] = w_conv[(o * C_ + c) * 3 + k];
    }
    if (i < C_ * O_) {
        int n = i % O_, c = i / O_;
        g_wn[i] = (n < C_) ? w_res[n * C_ + c] : w_skip[(n - C_) * C_ + c];
    }
}

__global__ void k_w2build() {
    int i = blockIdx.x * 256 + threadIdx.x;
    int n = i >> 9, kk = i & 511;
    int c = kk & 255, part = kk >> 8;
    float base = (part ? DZ : ZA) * g_wn[c * O_ + n];
    __half h = __float2half(base);
    __half l = __float2half(base - __half2float(h));
    g_w2[n * 1024 + kk] = h;
    g_w2[n * 1024 + 512 + kk] = l;
}

__global__ void k_wsplit(const float* __restrict__ w_conv) {
    int i = blockIdx.x * 256 + threadIdx.x;    // 512*256 (o,c)
    int o = i >> 8, c = i & 255;
    #pragma unroll
    for (int k = 0; k < 3; k++) {
        float w = w_conv[(o * C_ + c) * 3 + k] * WSC;
        __half h1 = __float2half_rn(w);
        float r1 = w - __half2float(h1);
        __half h2 = __float2half_rn(r1);
        size_t base = ((size_t)k * 512 + o) * 256 + c;
        g_wcs[0 * 393216 + base] = h1;     // sp=0
        g_wcs[1 * 393216 + base] = h2;     // sp=1
    }
}

__global__ void k_econv(const float* __restrict__ b_conv) {
    int b = blockIdx.x;
    int lo = threadIdx.x & 127;
    int half = threadIdx.x >> 7;
    int o = blockIdx.y * 128 + lo;
    __shared__ float pr[C_];
    __shared__ float red[3][128];
    for (int i = threadIdx.x; i < C_; i += 256) pr[i] = g_proj[b * C_ + i];
    __syncthreads();
    float e0 = 0.f, e1 = 0.f, e2 = 0.f;
    int c0 = half * 128;
    #pragma unroll 4
    for (int c = c0; c < c0 + 128; c++) {
        float p = pr[c];
        e0 += g_wc[(0 * C_ + c) * O_ + o] * p;
        e1 += g_wc[(1 * C_ + c) * O_ + o] * p;
        e2 += g_wc[(2 * C_ + c) * O_ + o] * p;
    }
    if (half) { red[0][lo] = e0; red[1][lo] = e1; red[2][lo] = e2; }
    __syncthreads();
    if (!half) {
        e0 += red[0][lo]; e1 += red[1][lo]; e2 += red[2][lo];
        g_base[b * O_ + o] = e0 + e1 + e2 + b_conv[o];
        g_e0[b * O_ + o] = e0;
        g_e2[b * O_ + o] = e2;
    }
}

// ---------------- conv1d + LIF via HMMA (fp16 2x2 split, 3 terms) ----------------
// grid (32 lt, 4 ot, 16 b), 256 threads, 2 CTA/SM.
// stage: ws[6 q][128 m][24 halves] = 36864B ; xs[2 sp][66 l][18 c] = 4752B
#define WS_SZ 36864
#define CSTAGE 41728
#define CONV_SMEM (2*CSTAGE + 2*9216)

__global__ void __launch_bounds__(256, 2) k_conv_mma(const float* __restrict__ x) {
    extern __shared__ char sm[];
    const u32 sb = smem_u32(sm);
    const int lt = blockIdx.x, ot = blockIdx.y, b = blockIdx.z;
    const int l0 = lt * 64;
    const int tid = threadIdx.x, wid = tid >> 5, lane = tid & 31;
    const int wn = wid >> 1, wl = wid & 1;
    const int r4 = lane >> 2, c2 = (lane & 3) * 2;

    __half* su  = (__half*)(sm + 2 * CSTAGE);
    __half* sw_ = (__half*)(sm + 2 * CSTAGE + 9216);

    auto load_step = [&](int step) {
        int t = step >> 4, cc = (step & 15) << 4, s = step & 1;
        u32 wsb = sb + s * CSTAGE;
        // weights: 1536 cp16 (6 per thread); q = sh*2+sp
        #pragma unroll
        for (int j = 0; j < 6; j++) {
            int idx = tid + j * 256;
            int c16 = idx & 1;
            int m = (idx >> 1) & 127;
            int q = idx >> 8;              // 0..5
            int sh = q >> 1, sp = q & 1;
            int o = (m < 64) ? (ot * 64 + m) : (256 + ot * 64 + m - 64);
            const __half* src = g_wcs + (((size_t)(sp * 3 + sh) * 512 + o) << 8) + cc + c16 * 8;
            cp16(wsb + (u32)((q * 128 + m) * 48 + c16 * 16), src);
        }
        asm volatile("cp.async.commit_group;" ::: "memory");
        // x tile: fp32 load -> 2-way fp16 split, transposed [l][c]
        __half* xs = (__half*)(sm + s * CSTAGE + WS_SZ);
        int c = tid >> 4, lb = tid & 15;
        const float* xr = x + ((size_t)((t * B_ + b) * C_) + cc + c) * L_;
        #pragma unroll
        for (int k = 0; k < 5; k++) {
            int li = lb + k * 16;
            if (li < 66) {
                int gl = l0 - 1 + li;
                float v = 0.f;
                if (gl >= 0 && gl < L_) v = xr[gl] * XS;
                __half h1 = __float2half_rn(v);
                float r1 = v - __half2float(h1);
                __half h2 = __float2half_rn(r1);
                xs[(0 * 66 + li) * 18 + c] = h1;
                xs[(1 * 66 + li) * 18 + c] = h2;
            }
        }
    };

    float acc[2][4][4];
    float v[2][2][8];
    #pragma unroll
    for (int m = 0; m < 2; m++)
        #pragma unroll
        for (int j = 0; j < 4; j++)
            #pragma unroll
            for (int e = 0; e < 4; e++) acc[m][j][e] = 0.f;
    #pragma unroll
    for (int g = 0; g < 2; g++)
        #pragma unroll
        for (int h = 0; h < 2; h++)
            #pragma unroll
            for (int e = 0; e < 8; e++) v[g][h][e] = 0.f;

    load_step(0);
    load_step(1);

    const __half one = __float2half(1.f), zero = __float2half(0.f);

    #pragma unroll 1
    for (int step = 0; step < 64; step++) {
        if (step < 62) asm volatile("cp.async.wait_group 1;" ::: "memory");
        else           asm volatile("cp.async.wait_group 0;" ::: "memory");
        __syncthreads();
        int s = step & 1;
        const char* wsb = sm + s * CSTAGE;
        const __half* xs = (const __half*)(sm + s * CSTAGE + WS_SZ);

        #pragma unroll
        for (int sh = 0; sh < 3; sh++) {
            u32 bf0[2][4], bf1[2][4];
            #pragma unroll
            for (int sp = 0; sp < 2; sp++)
                #pragma unroll
                for (int j = 0; j < 4; j++) {
                    const __half* p = xs + (sp * 66 + wl * 32 + j * 8 + r4 + sh) * 18 + c2;
                    bf0[sp][j] = *(const u32*)p;
                    bf1[sp][j] = *(const u32*)(p + 8);
                }
            u32 a[2][2][4];
            #pragma unroll
            for (int sp = 0; sp < 2; sp++)
                #pragma unroll
                for (int m = 0; m < 2; m++) {
                    const __half* p = (const __half*)(wsb + ((sh * 2 + sp) * 128 + m * 64 + wn * 16 + r4) * 48) + c2;
                    a[sp][m][0] = *(const u32*)p;
                    a[sp][m][1] = *(const u32*)(p + 8 * 24);
                    a[sp][m][2] = *(const u32*)(p + 8);
                    a[sp][m][3] = *(const u32*)(p + 8 * 24 + 8);
                }
            #pragma unroll
            for (int m = 0; m < 2; m++)
                #pragma unroll
                for (int j = 0; j < 4; j++) {
                    #define TRM(xi, wi) mma16816(acc[m][j], a[wi][m][0], a[wi][m][1], a[wi][m][2], a[wi][m][3], bf0[xi][j], bf1[xi][j])
                    TRM(0, 0); TRM(0, 1); TRM(1, 0);
                    #undef TRM
                }
        }
        __syncthreads();
        if (step + 2 < 64) load_step(step + 2);

        if ((step & 15) == 15) {   // epilogue for this t
            int t = step >> 4;
            int chb = ot * 64 + wn * 16 + r4;
            #pragma unroll
            for (int h = 0; h < 2; h++) {
                int cg = chb + h * 8;
                int cf = cg + 256;
                float bg0 = g_base[b * O_ + cg], bf0v = g_base[b * O_ + cf];
                float e0g = g_e0[b * O_ + cg], e0f = g_e0[b * O_ + cf];
                float e2g = g_e2[b * O_ + cg], e2f = g_e2[b * O_ + cf];
                #pragma unroll
                for (int j = 0; j < 4; j++)
                    #pragma unroll
                    for (int e = 0; e < 2; e++) {
                        int ll = wl * 32 + j * 8 + c2 + e;
                        int gl = l0 + ll;
                        float bg = bg0, bfv = bf0v;
                        if (gl == 0)      { bg -= e0g; bfv -= e0f; }
                        if (gl == L_ - 1) { bg -= e2g; bfv -= e2f; }
                        float yg = acc[0][j][h * 2 + e] * INV_SC + bg;
                        float yf = acc[1][j][h * 2 + e] * INV_SC + bfv;
                        int vi = j * 2 + e;
                        float vg = v[0][h][vi]; vg = vg + (yg - vg) / 1.2f;
                        float vf = v[1][h][vi]; vf = vf + (yf - vf) / 1.2f;
                        bool sg = vg >= 0.5f, sf = vf >= 0.5f;
                        v[0][h][vi] = sg ? 0.f : vg;
                        v[1][h][vi] = sf ? 0.f : vf;
                        su[ll * 72 + wn * 16 + r4 + h * 8] = sf ? one : zero;
                        sw_[ll * 72 + wn * 16 + r4 + h * 8] = (sf && sg) ? one : zero;
                    }
            }
            #pragma unroll
            for (int m = 0; m < 2; m++)
                #pragma unroll
                for (int j = 0; j < 4; j++)
                    #pragma unroll
                    for (int e = 0; e < 4; e++) acc[m][j][e] = 0.f;
            __syncthreads();
            {
                int row = tid >> 2, seg = tid & 3;
                __half* dst = g_s + ((size_t)(t * B_ + b) * L_ + l0 + row) * 512;
                uint4 a0 = *(uint4*)&su[row * 72 + seg * 16];
                uint4 a1 = *(uint4*)&su[row * 72 + seg * 16 + 8];
                uint4 b0 = *(uint4*)&sw_[row * 72 + seg * 16];
                uint4 b1 = *(uint4*)&sw_[row * 72 + seg * 16 + 8];
                *(uint4*)(dst + ot * 64 + seg * 16)           = a0;
                *(uint4*)(dst + ot * 64 + seg * 16 + 8)       = a1;
                *(uint4*)(dst + 256 + ot * 64 + seg * 16)     = b0;
                *(uint4*)(dst + 256 + ot * 64 + seg * 16 + 8) = b1;
            }
            __syncthreads();
        }
    }
}

// ---------------- output GEMM via mma.sync (HMMA) ----------------
#define SMEM_OUT 61440
#define RS 40

__global__ void __launch_bounds__(256) k_out_mma(const float* __restrict__ x,
                                                 const float* __restrict__ b_skip,
                                                 const float* __restrict__ b_res,
                                                 float* __restrict__ out) {
    extern __shared__ __half smo[];
    const int lt = blockIdx.x, nt = blockIdx.y, tb = blockIdx.z;
    const int tid = threadIdx.x;
    const int wid = tid >> 5, lane = tid & 31;
    const int wn = wid >> 1;
    const int wl = wid & 1;
    const u32 sb = smem_u32(smo);

    const __half* gS = g_s + ((size_t)tb * L_ + lt * 128) * 512;
    const __half* gW = g_w2 + (size_t)(nt * 128) * 1024;

    float acc[2][8][4];
    #pragma unroll
    for (int m = 0; m < 2; m++)
        #pragma unroll
        for (int j = 0; j < 8; j++)
            #pragma unroll
            for (int e = 0; e < 4; e++) acc[m][j][e] = 0.f;

    auto load_chunk = [&](int c) {
        int s = c & 1;
        int k0 = c * 32;
        u32 sS = sb + s * 10240;
        u32 sH = sb + 20480 + s * 10240;
        u32 sL = sb + 40960 + s * 10240;
        #pragma unroll
        for (int j = 0; j < 2; j++) {
            int vv = tid + j * 256;
            int r = vv >> 2, c16 = vv & 3;
            u32 doff = (u32)(r * RS + c16 * 8) * 2;
            cp16(sS + doff, gS + (size_t)r * 512 + k0 + c16 * 8);
            cp16(sH + doff, gW + (size_t)r * 1024 + k0 + c16 * 8);
            cp16(sL + doff, gW + (size_t)r * 1024 + 512 + k0 + c16 * 8);
        }
        asm volatile("cp.async.commit_group;" ::: "memory");
    };

    load_chunk(0);
    load_chunk(1);

    const int r4 = lane >> 2, c2 = 2 * (lane & 3);

    #pragma unroll 1
    for (int c = 0; c < 16; c++) {
        if (c + 2 < 16) asm volatile("cp.async.wait_group 1;" ::: "memory");
        else            asm volatile("cp.async.wait_group 0;" ::: "memory");
        __syncthreads();
        int s = c & 1;
        const __half* S  = smo + s * 5120;
        const __half* WH = smo + 10240 + s * 5120;
        const __half* WL = smo + 20480 + s * 5120;

        #pragma unroll
        for (int ks = 0; ks < 2; ks++) {
            int k0s = ks * 16;
            u32 bs0[8], bs1[8];
            #pragma unroll
            for (int j = 0; j < 8; j++) {
                int l = wl * 64 + j * 8 + r4;
                const __half* p = S + l * RS + k0s + c2;
                bs0[j] = *(const u32*)p;
                bs1[j] = *(const u32*)(p + 8);
            }
            #pragma unroll
            for (int m = 0; m < 2; m++) {
                int row = wn * 32 + m * 16 + r4;
                #pragma unroll
                for (int sp = 0; sp < 2; sp++) {
                    const __half* W = sp ? WL : WH;
                    const __half* p = W + row * RS + k0s + c2;
                    u32 a0 = *(const u32*)p;
                    u32 a1 = *(const u32*)(p + 8 * RS);
                    u32 a2 = *(const u32*)(p + 8);
                    u32 a3 = *(const u32*)(p + 8 * RS + 8);
                    #pragma unroll
                    for (int j = 0; j < 8; j++)
                        mma16816(acc[m][j], a0, a1, a2, a3, bs0[j], bs1[j]);
                }
            }
        }
        __syncthreads();
        if (c + 2 < 16) load_chunk(c + 2);
    }

    size_t base_tb = (size_t)tb * C_ * L_;
    #pragma unroll
    for (int m = 0; m < 2; m++) {
        #pragma unroll
        for (int j = 0; j < 8; j++) {
            int lg = lt * 128 + wl * 64 + j * 8 + c2;
            #pragma unroll
            for (int half = 0; half < 2; half++) {
                int ng = nt * 128 + wn * 32 + m * 16 + r4 + half * 8;
                float v0 = acc[m][j][half * 2], v1 = acc[m][j][half * 2 + 1];
                if (ng < 256) {
                    size_t idx = base_tb + (size_t)ng * L_ + lg;
                    float bias = b_res[ng];
                    float2 xv = *(const float2*)(x + idx);
                    *(float2*)(out + idx) = make_float2(v0 + xv.x + bias, v1 + xv.y + bias);
                } else {
                    int o = ng - 256;
                    size_t idx = base_tb + (size_t)o * L_ + lg;
                    float bias = b_skip[o];
                    *(float2*)(out + TBCL_ + idx) = make_float2(v0 + bias, v1 + bias);
                }
            }
        }
    }
}

extern "C" void kernel_launch(void* const* d_in, const int* in_sizes, int n_in,
                              void* d_out, int out_size) {
    const float* x      = (const float*)d_in[0];
    const int*   dstep  = (const int*)d_in[1];
    const float* w_emb1 = (const float*)d_in[2];
    const float* b_emb1 = (const float*)d_in[3];
    const float* w_emb2 = (const float*)d_in[4];
    const float* b_emb2 = (const float*)d_in[5];
    const float* w_proj = (const float*)d_in[6];
    const float* b_proj = (const float*)d_in[7];
    const float* w_conv = (const float*)d_in[8];
    const float* b_conv = (const float*)d_in[9];
    const float* w_skip = (const float*)d_in[10];
    const float* b_skip = (const float*)d_in[11];
    const float* w_res  = (const float*)d_in[12];
    const float* b_res  = (const float*)d_in[13];
    float* out = (float*)d_out;

    static int attr_set = 0;
    if (!attr_set) {
        cudaFuncSetAttribute(k_out_mma, cudaFuncAttributeMaxDynamicSharedMemorySize, SMEM_OUT);
        cudaFuncSetAttribute(k_conv_mma, cudaFuncAttributeMaxDynamicSharedMemorySize, CONV_SMEM);
        attr_set = 1;
    }

    k_proj<<<B_, C_>>>(dstep, w_emb1, b_emb1, w_emb2, b_emb2, w_proj, b_proj);
    k_wtrans<<<(3 * C_ * O_ + 255) / 256, 256>>>(w_conv, w_skip, w_res);
    k_w2build<<<512 * 512 / 256, 256>>>();
    k_wsplit<<<512 * 256 / 256, 256>>>(w_conv);
    k_econv<<<dim3(B_, O_ / 128), 256>>>(b_conv);
    k_conv_mma<<<dim3(32, 4, 16), 256, CONV_SMEM>>>(x);
    k_out_mma<<<dim3(16, 4, 64), 256, SMEM_OUT>>>(x, b_skip, b_res, out);
}

// round 10
// speedup vs baseline: 1.9498x; 1.0928x over previous
#include <cuda_runtime.h>
#include <cuda_fp16.h>
#include <math.h>
#include <stdint.h>

#define T_ 4
#define B_ 16
#define C_ 256
#define L_ 2048
#define O_ 512
#define TBCL_ (T_*B_*C_*L_)
#define ZA 0.38079708f
#define ZB 0.55676994f
#define DZ (ZB - ZA)
#define XS 16.0f
#define WSC 128.0f
#define INV_SC (1.0f/2048.0f)

typedef unsigned long long u64;
typedef uint32_t u32;

__device__ __forceinline__ u32 smem_u32(const void* p) {
    u32 a;
    asm("{ .reg .u64 t; cvta.to.shared.u64 t, %1; cvt.u32.u64 %0, t; }" : "=r"(a) : "l"(p));
    return a;
}
__device__ __forceinline__ void cp16(u32 dst, const void* src) {
    asm volatile("cp.async.cg.shared.global [%0], [%1], 16;" :: "r"(dst), "l"(src));
}
__device__ __forceinline__ void cp16z(u32 dst, const void* src, bool ok) {
    int sz = ok ? 16 : 0;
    asm volatile("cp.async.cg.shared.global [%0], [%1], 16, %2;" :: "r"(dst), "l"(src), "r"(sz));
}
__device__ __forceinline__ void mma16816(float* c, u32 a0, u32 a1, u32 a2, u32 a3, u32 b0, u32 b1) {
    asm volatile("mma.sync.aligned.m16n8k16.row.col.f32.f16.f16.f32 "
                 "{%0,%1,%2,%3},{%4,%5,%6,%7},{%8,%9},{%0,%1,%2,%3};"
                 : "+f"(c[0]), "+f"(c[1]), "+f"(c[2]), "+f"(c[3])
                 : "r"(a0), "r"(a1), "r"(a2), "r"(a3), "r"(b0), "r"(b1));
}

// ---- device scratch ----
__device__ __half g_s[(size_t)T_*B_*L_*512];   // spikes [tb][l][512] = [u(256)|w(256)]
__device__ __half g_xt[(size_t)T_*B_*L_*512];  // x splits [tb][l][hi(256)|lo(256)], x16
__device__ __half g_w2[512 * 512];             // out-GEMM weights [n][512] (hi only)
__device__ __half g_wcs[6 * 512 * 256];        // conv w splits [sp][sh][o][c], x128
__device__ float g_proj[B_*C_];
__device__ float g_base[B_*O_];
__device__ float g_e0[B_*O_];
__device__ float g_e2[B_*O_];
__device__ float g_wc[3*C_*O_];                // [k][c][o] fp32 (for k_econv)

// ---------------- prep kernels ----------------
__global__ void k_proj(const int* __restrict__ dstep,
                       const float* __restrict__ w1, const float* __restrict__ b1,
                       const float* __restrict__ w2, const float* __restrict__ b2,
                       const float* __restrict__ wp, const float* __restrict__ bp) {
    int b = blockIdx.x, c = threadIdx.x;
    __shared__ float h[C_], emb[C_];
    float ds = (float)dstep[b];
    float t1 = ds * w1[c] + b1[c];
    h[c] = t1 / (1.f + expf(-t1));
    __syncthreads();
    float e = b2[c];
    const float* w2r = w2 + c * C_;
    for (int j = 0; j < C_; j++) e += w2r[j] * h[j];
    __syncthreads();
    emb[c] = e;
    __syncthreads();
    float p = bp[c];
    const float* wpr = wp + c * C_;
    for (int j = 0; j < C_; j++) p += wpr[j] * emb[j];
    g_proj[b * C_ + c] = p;
}

__global__ void k_wtrans(const float* __restrict__ w_conv) {
    int i = blockIdx.x * 256 + threadIdx.x;
    if (i < 3 * C_ * O_) {
        int o = i % O_, c = (i / O_) % C_, k = i / (O_ * C_);
        g_wc[i] = w_conv[(o * C_ + c) * 3 + k];
    }
}

__global__ void k_w2build(const float* __restrict__ w_skip, const float* __restrict__ w_res) {
    int i = blockIdx.x * 256 + threadIdx.x;   // 512*512: (n, kk)
    int n = i >> 9, kk = i & 511;
    int c = kk & 255, part = kk >> 8;
    float wv = (n < 256) ? w_res[n * C_ + c] : w_skip[(n - 256) * C_ + c];
    g_w2[n * 512 + kk] = __float2half((part ? DZ : ZA) * wv);
}

__global__ void k_wsplit(const float* __restrict__ w_conv) {
    int i = blockIdx.x * 256 + threadIdx.x;    // 512*256 (o,c)
    int o = i >> 8, c = i & 255;
    #pragma unroll
    for (int k = 0; k < 3; k++) {
        float w = w_conv[(o * C_ + c) * 3 + k] * WSC;
        __half h1 = __float2half_rn(w);
        float r1 = w - __half2float(h1);
        __half h2 = __float2half_rn(r1);
        size_t base = ((size_t)k * 512 + o) * 256 + c;
        g_wcs[0 * 393216 + base] = h1;
        g_wcs[1 * 393216 + base] = h2;
    }
}

// x transpose+split: [tb][c][l] f32 -> [tb][l][hi|lo] fp16, scaled by 16
__global__ void k_xsplit(const float* __restrict__ x) {
    __shared__ float tile[32][33];
    int tb = blockIdx.z;
    int c0 = blockIdx.y * 32, l0 = blockIdx.x * 32;
    int tx = threadIdx.x & 31, ty = threadIdx.x >> 5;   // 32x8
    const float* xb = x + ((size_t)tb * C_ + c0) * L_ + l0;
    #pragma unroll
    for (int i = 0; i < 4; i++)
        tile[ty + i * 8][tx] = xb[(size_t)(ty + i * 8) * L_ + tx];
    __syncthreads();
    __half* dst = g_xt + ((size_t)tb * L_ + l0) * 512 + c0;
    #pragma unroll
    for (int i = 0; i < 4; i++) {
        int l = ty + i * 8;
        float v = tile[tx][l] * XS;
        __half h1 = __float2half_rn(v);
        __half h2 = __float2half_rn(v - __half2float(h1));
        dst[(size_t)l * 512 + tx] = h1;
        dst[(size_t)l * 512 + 256 + tx] = h2;
    }
}

__global__ void k_econv(const float* __restrict__ b_conv) {
    int b = blockIdx.x;
    int lo = threadIdx.x & 127;
    int half = threadIdx.x >> 7;
    int o = blockIdx.y * 128 + lo;
    __shared__ float pr[C_];
    __shared__ float red[3][128];
    for (int i = threadIdx.x; i < C_; i += 256) pr[i] = g_proj[b * C_ + i];
    __syncthreads();
    float e0 = 0.f, e1 = 0.f, e2 = 0.f;
    int c0 = half * 128;
    #pragma unroll 4
    for (int c = c0; c < c0 + 128; c++) {
        float p = pr[c];
        e0 += g_wc[(0 * C_ + c) * O_ + o] * p;
        e1 += g_wc[(1 * C_ + c) * O_ + o] * p;
        e2 += g_wc[(2 * C_ + c) * O_ + o] * p;
    }
    if (half) { red[0][lo] = e0; red[1][lo] = e1; red[2][lo] = e2; }
    __syncthreads();
    if (!half) {
        e0 += red[0][lo]; e1 += red[1][lo]; e2 += red[2][lo];
        g_base[b * O_ + o] = e0 + e1 + e2 + b_conv[o];
        g_e0[b * O_ + o] = e0;
        g_e2[b * O_ + o] = e2;
    }
}

// ---------------- conv1d + LIF via HMMA (fp16 2x2 split, 3 terms) ----------------
// grid (32 lt, 4 ot, 16 b), 256 threads, 2 CTA/SM.
// stage: ws[6 q][128 m][24 halves] = 36864B ; xs[2 sp][66 l][24 halves] = 6336B
#define WS_SZ 36864
#define CSTAGE 43200
#define CONV_SMEM (2*CSTAGE + 2*9216)

__global__ void __launch_bounds__(256, 2) k_conv_mma(const float* __restrict__ x) {
    extern __shared__ char sm[];
    const u32 sb = smem_u32(sm);
    const int lt = blockIdx.x, ot = blockIdx.y, b = blockIdx.z;
    const int l0 = lt * 64;
    const int tid = threadIdx.x, wid = tid >> 5, lane = tid & 31;
    const int wn = wid >> 1, wl = wid & 1;
    const int r4 = lane >> 2, c2 = (lane & 3) * 2;

    __half* su  = (__half*)(sm + 2 * CSTAGE);
    __half* sw_ = (__half*)(sm + 2 * CSTAGE + 9216);

    auto load_step = [&](int step) {
        int t = step >> 4, cc = (step & 15) << 4, s = step & 1;
        u32 wsb = sb + s * CSTAGE;
        // weights: 1536 cp16 (6 per thread); q = sh*2+sp
        #pragma unroll
        for (int j = 0; j < 6; j++) {
            int idx = tid + j * 256;
            int c16 = idx & 1;
            int m = (idx >> 1) & 127;
            int q = idx >> 8;              // 0..5
            int sh = q >> 1, sp = q & 1;
            int o = (m < 64) ? (ot * 64 + m) : (256 + ot * 64 + m - 64);
            const __half* src = g_wcs + (((size_t)(sp * 3 + sh) * 512 + o) << 8) + cc + c16 * 8;
            cp16(wsb + (u32)((q * 128 + m) * 48 + c16 * 16), src);
        }
        // x tile: 264 cp16 from presplit g_xt (zero-fill halo)
        const __half* xb = g_xt + ((size_t)(t * B_ + b) * L_) * 512;
        u32 xsb = sb + s * CSTAGE + WS_SZ;
        #pragma unroll
        for (int j = 0; j < 2; j++) {
            int u = tid + j * 256;
            if (u < 264) {
                int li = u >> 2, q = u & 3;
                int sp = q >> 1, h16 = q & 1;
                int gl = l0 - 1 + li;
                bool ok = (gl >= 0 && gl < L_);
                int glc = ok ? gl : 0;
                const __half* src = xb + (size_t)glc * 512 + sp * 256 + cc + h16 * 8;
                cp16z(xsb + (u32)(((sp * 66 + li) * 24 + h16 * 8) * 2), src, ok);
            }
        }
        asm volatile("cp.async.commit_group;" ::: "memory");
    };

    float acc[2][4][4];
    float v[2][2][8];
    #pragma unroll
    for (int m = 0; m < 2; m++)
        #pragma unroll
        for (int j = 0; j < 4; j++)
            #pragma unroll
            for (int e = 0; e < 4; e++) acc[m][j][e] = 0.f;
    #pragma unroll
    for (int g = 0; g < 2; g++)
        #pragma unroll
        for (int h = 0; h < 2; h++)
            #pragma unroll
            for (int e = 0; e < 8; e++) v[g][h][e] = 0.f;

    load_step(0);
    load_step(1);

    const __half one = __float2half(1.f), zero = __float2half(0.f);

    #pragma unroll 1
    for (int step = 0; step < 64; step++) {
        if (step < 62) asm volatile("cp.async.wait_group 1;" ::: "memory");
        else           asm volatile("cp.async.wait_group 0;" ::: "memory");
        __syncthreads();
        int s = step & 1;
        const char* wsb = sm + s * CSTAGE;
        const __half* xs = (const __half*)(sm + s * CSTAGE + WS_SZ);

        #pragma unroll
        for (int sh = 0; sh < 3; sh++) {
            u32 bf0[2][4], bf1[2][4];
            #pragma unroll
            for (int sp = 0; sp < 2; sp++)
                #pragma unroll
                for (int j = 0; j < 4; j++) {
                    const __half* p = xs + (sp * 66 + wl * 32 + j * 8 + r4 + sh) * 24 + c2;
                    bf0[sp][j] = *(const u32*)p;
                    bf1[sp][j] = *(const u32*)(p + 8);
                }
            u32 a[2][2][4];
            #pragma unroll
            for (int sp = 0; sp < 2; sp++)
                #pragma unroll
                for (int m = 0; m < 2; m++) {
                    const __half* p = (const __half*)(wsb + ((sh * 2 + sp) * 128 + m * 64 + wn * 16 + r4) * 48) + c2;
                    a[sp][m][0] = *(const u32*)p;
                    a[sp][m][1] = *(const u32*)(p + 8 * 24);
                    a[sp][m][2] = *(const u32*)(p + 8);
                    a[sp][m][3] = *(const u32*)(p + 8 * 24 + 8);
                }
            #pragma unroll
            for (int m = 0; m < 2; m++)
                #pragma unroll
                for (int j = 0; j < 4; j++) {
                    #define TRM(xi, wi) mma16816(acc[m][j], a[wi][m][0], a[wi][m][1], a[wi][m][2], a[wi][m][3], bf0[xi][j], bf1[xi][j])
                    TRM(0, 0); TRM(0, 1); TRM(1, 0);
                    #undef TRM
                }
        }
        __syncthreads();
        if (step + 2 < 64) load_step(step + 2);

        if ((step & 15) == 15) {   // epilogue for this t
            int t = step >> 4;
            int chb = ot * 64 + wn * 16 + r4;
            #pragma unroll
            for (int h = 0; h < 2; h++) {
                int cg = chb + h * 8;
                int cf = cg + 256;
                float bg0 = g_base[b * O_ + cg], bf0v = g_base[b * O_ + cf];
                float e0g = g_e0[b * O_ + cg], e0f = g_e0[b * O_ + cf];
                float e2g = g_e2[b * O_ + cg], e2f = g_e2[b * O_ + cf];
                #pragma unroll
                for (int j = 0; j < 4; j++)
                    #pragma unroll
                    for (int e = 0; e < 2; e++) {
                        int ll = wl * 32 + j * 8 + c2 + e;
                        int gl = l0 + ll;
                        float bg = bg0, bfv = bf0v;
                        if (gl == 0)      { bg -= e0g; bfv -= e0f; }
                        if (gl == L_ - 1) { bg -= e2g; bfv -= e2f; }
                        float yg = acc[0][j][h * 2 + e] * INV_SC + bg;
                        float yf = acc[1][j][h * 2 + e] * INV_SC + bfv;
                        int vi = j * 2 + e;
                        float vg = v[0][h][vi]; vg = vg + (yg - vg) / 1.2f;
                        float vf = v[1][h][vi]; vf = vf + (yf - vf) / 1.2f;
                        bool sg = vg >= 0.5f, sf = vf >= 0.5f;
                        v[0][h][vi] = sg ? 0.f : vg;
                        v[1][h][vi] = sf ? 0.f : vf;
                        su[ll * 72 + wn * 16 + r4 + h * 8] = sf ? one : zero;
                        sw_[ll * 72 + wn * 16 + r4 + h * 8] = (sf && sg) ? one : zero;
                    }
            }
            #pragma unroll
            for (int m = 0; m < 2; m++)
                #pragma unroll
                for (int j = 0; j < 4; j++)
                    #pragma unroll
                    for (int e = 0; e < 4; e++) acc[m][j][e] = 0.f;
            __syncthreads();
            {
                int row = tid >> 2, seg = tid & 3;
                __half* dst = g_s + ((size_t)(t * B_ + b) * L_ + l0 + row) * 512;
                uint4 a0 = *(uint4*)&su[row * 72 + seg * 16];
                uint4 a1 = *(uint4*)&su[row * 72 + seg * 16 + 8];
                uint4 b0 = *(uint4*)&sw_[row * 72 + seg * 16];
                uint4 b1 = *(uint4*)&sw_[row * 72 + seg * 16 + 8];
                *(uint4*)(dst + ot * 64 + seg * 16)           = a0;
                *(uint4*)(dst + ot * 64 + seg * 16 + 8)       = a1;
                *(uint4*)(dst + 256 + ot * 64 + seg * 16)     = b0;
                *(uint4*)(dst + 256 + ot * 64 + seg * 16 + 8) = b1;
            }
            __syncthreads();
        }
    }
}

// ---------------- output GEMM via mma.sync (HMMA), single split ----------------
#define SMEM_OUT 40960
#define RS 40

__global__ void __launch_bounds__(256) k_out_mma(const float* __restrict__ x,
                                                 const float* __restrict__ b_skip,
                                                 const float* __restrict__ b_res,
                                                 float* __restrict__ out) {
    extern __shared__ __half smo[];
    const int lt = blockIdx.x, nt = blockIdx.y, tb = blockIdx.z;
    const int tid = threadIdx.x;
    const int wid = tid >> 5, lane = tid & 31;
    const int wn = wid >> 1;
    const int wl = wid & 1;
    const u32 sb = smem_u32(smo);

    const __half* gS = g_s + ((size_t)tb * L_ + lt * 128) * 512;
    const __half* gW = g_w2 + (size_t)(nt * 128) * 512;

    float acc[2][8][4];
    #pragma unroll
    for (int m = 0; m < 2; m++)
        #pragma unroll
        for (int j = 0; j < 8; j++)
            #pragma unroll
            for (int e = 0; e < 4; e++) acc[m][j][e] = 0.f;

    auto load_chunk = [&](int c) {
        int s = c & 1;
        int k0 = c * 32;
        u32 sS = sb + s * 10240;
        u32 sH = sb + 20480 + s * 10240;
        #pragma unroll
        for (int j = 0; j < 2; j++) {
            int vv = tid + j * 256;           // 0..511
            int r = vv >> 2, c16 = vv & 3;
            u32 doff = (u32)(r * RS + c16 * 8) * 2;
            cp16(sS + doff, gS + (size_t)r * 512 + k0 + c16 * 8);
            cp16(sH + doff, gW + (size_t)r * 512 + k0 + c16 * 8);
        }
        asm volatile("cp.async.commit_group;" ::: "memory");
    };

    load_chunk(0);
    load_chunk(1);

    const int r4 = lane >> 2, c2 = 2 * (lane & 3);

    #pragma unroll 1
    for (int c = 0; c < 16; c++) {
        if (c + 2 < 16) asm volatile("cp.async.wait_group 1;" ::: "memory");
        else            asm volatile("cp.async.wait_group 0;" ::: "memory");
        __syncthreads();
        int s = c & 1;
        const __half* S  = smo + s * 5120;
        const __half* WH = smo + 10240 + s * 5120;

        #pragma unroll
        for (int ks = 0; ks < 2; ks++) {
            int k0s = ks * 16;
            u32 bs0[8], bs1[8];
            #pragma unroll
            for (int j = 0; j < 8; j++) {
                int l = wl * 64 + j * 8 + r4;
                const __half* p = S + l * RS + k0s + c2;
                bs0[j] = *(const u32*)p;
                bs1[j] = *(const u32*)(p + 8);
            }
            #pragma unroll
            for (int m = 0; m < 2; m++) {
                int row = wn * 32 + m * 16 + r4;
                const __half* p = WH + row * RS + k0s + c2;
                u32 a0 = *(const u32*)p;
                u32 a1 = *(const u32*)(p + 8 * RS);
                u32 a2 = *(const u32*)(p + 8);
                u32 a3 = *(const u32*)(p + 8 * RS + 8);
                #pragma unroll
                for (int j = 0; j < 8; j++)
                    mma16816(acc[m][j], a0, a1, a2, a3, bs0[j], bs1[j]);
            }
        }
        __syncthreads();
        if (c + 2 < 16) load_chunk(c + 2);
    }

    size_t base_tb = (size_t)tb * C_ * L_;
    #pragma unroll
    for (int m = 0; m < 2; m++) {
        #pragma unroll
        for (int j = 0; j < 8; j++) {
            int lg = lt * 128 + wl * 64 + j * 8 + c2;
            #pragma unroll
            for (int half = 0; half < 2; half++) {
                int ng = nt * 128 + wn * 32 + m * 16 + r4 + half * 8;
                float v0 = acc[m][j][half * 2], v1 = acc[m][j][half * 2 + 1];
                if (ng < 256) {
                    size_t idx = base_tb + (size_t)ng * L_ + lg;
                    float bias = b_res[ng];
                    float2 xv = *(const float2*)(x + idx);
                    *(float2*)(out + idx) = make_float2(v0 + xv.x + bias, v1 + xv.y + bias);
                } else {
                    int o = ng - 256;
                    size_t idx = base_tb + (size_t)o * L_ + lg;
                    float bias = b_skip[o];
                    *(float2*)(out + TBCL_ + idx) = make_float2(v0 + bias, v1 + bias);
                }
            }
        }
    }
}

extern "C" void kernel_launch(void* const* d_in, const int* in_sizes, int n_in,
                              void* d_out, int out_size) {
    const float* x      = (const float*)d_in[0];
    const int*   dstep  = (const int*)d_in[1];
    const float* w_emb1 = (const float*)d_in[2];
    const float* b_emb1 = (const float*)d_in[3];
    const float* w_emb2 = (const float*)d_in[4];
    const float* b_emb2 = (const float*)d_in[5];
    const float* w_proj = (const float*)d_in[6];
    const float* b_proj = (const float*)d_in[7];
    const float* w_conv = (const float*)d_in[8];
    const float* b_conv = (const float*)d_in[9];
    const float* w_skip = (const float*)d_in[10];
    const float* b_skip = (const float*)d_in[11];
    const float* w_res  = (const float*)d_in[12];
    const float* b_res  = (const float*)d_in[13];
    float* out = (float*)d_out;

    static int attr_set = 0;
    if (!attr_set) {
        cudaFuncSetAttribute(k_out_mma, cudaFuncAttributeMaxDynamicSharedMemorySize, SMEM_OUT);
        cudaFuncSetAttribute(k_conv_mma, cudaFuncAttributeMaxDynamicSharedMemorySize, CONV_SMEM);
        attr_set = 1;
    }

    k_proj<<<B_, C_>>>(dstep, w_emb1, b_emb1, w_emb2, b_emb2, w_proj, b_proj);
    k_wtrans<<<(3 * C_ * O_ + 255) / 256, 256>>>(w_conv);
    k_w2build<<<512 * 512 / 256, 256>>>(w_skip, w_res);
    k_wsplit<<<512 * 256 / 256, 256>>>(w_conv);
    k_xsplit<<<dim3(L_ / 32, C_ / 32, T_ * B_), 256>>>(x);
    k_econv<<<dim3(B_, O_ / 128), 256>>>(b_conv);
    k_conv_mma<<<dim3(32, 4, 16), 256, CONV_SMEM>>>(x);
    k_out_mma<<<dim3(16, 4, 64), 256, SMEM_OUT>>>(x, b_skip, b_res, out);
}

// round 11
// speedup vs baseline: 2.1199x; 1.0872x over previous
#include <cuda_runtime.h>
#include <cuda_fp16.h>
#include <math.h>
#include <stdint.h>

#define T_ 4
#define B_ 16
#define C_ 256
#define L_ 2048
#define O_ 512
#define TBCL_ (T_*B_*C_*L_)
#define ZA 0.38079708f
#define ZB 0.55676994f
#define DZ (ZB - ZA)
#define XS 16.0f
#define WSC 128.0f
#define INV_SC (1.0f/2048.0f)

typedef unsigned long long u64;
typedef uint32_t u32;

__device__ __forceinline__ u32 smem_u32(const void* p) {
    u32 a;
    asm("{ .reg .u64 t; cvta.to.shared.u64 t, %1; cvt.u32.u64 %0, t; }" : "=r"(a) : "l"(p));
    return a;
}
__device__ __forceinline__ void cp16(u32 dst, const void* src) {
    asm volatile("cp.async.cg.shared.global [%0], [%1], 16;" :: "r"(dst), "l"(src));
}
__device__ __forceinline__ void cp16z(u32 dst, const void* src, bool ok) {
    int sz = ok ? 16 : 0;
    asm volatile("cp.async.cg.shared.global [%0], [%1], 16, %2;" :: "r"(dst), "l"(src), "r"(sz));
}
__device__ __forceinline__ void mma16816(float* c, u32 a0, u32 a1, u32 a2, u32 a3, u32 b0, u32 b1) {
    asm volatile("mma.sync.aligned.m16n8k16.row.col.f32.f16.f16.f32 "
                 "{%0,%1,%2,%3},{%4,%5,%6,%7},{%8,%9},{%0,%1,%2,%3};"
                 : "+f"(c[0]), "+f"(c[1]), "+f"(c[2]), "+f"(c[3])
                 : "r"(a0), "r"(a1), "r"(a2), "r"(a3), "r"(b0), "r"(b1));
}

// ---- device scratch ----
__device__ __half g_s[(size_t)T_*B_*L_*512];   // spikes [tb][l][512] = [u(256)|w(256)]
__device__ __half g_xt[(size_t)T_*B_*L_*512];  // x splits [tb][l][hi(256)|lo(256)], x16
__device__ __half g_w2[512 * 512];             // out-GEMM weights [n][512] (hi only)
__device__ __half g_wcs[6 * 512 * 256];        // conv w splits [sp][sh][o][c], x128
__device__ float g_proj[B_*C_];
__device__ float g_base[B_*O_];
__device__ float g_e0[B_*O_];
__device__ float g_e2[B_*O_];
__device__ float g_wc[3*C_*O_];                // [k][c][o] fp32 (for k_econv)

// ---------------- prep kernels ----------------
__global__ void k_proj(const int* __restrict__ dstep,
                       const float* __restrict__ w1, const float* __restrict__ b1,
                       const float* __restrict__ w2, const float* __restrict__ b2,
                       const float* __restrict__ wp, const float* __restrict__ bp) {
    int b = blockIdx.x, c = threadIdx.x;
    __shared__ float h[C_], emb[C_];
    float ds = (float)dstep[b];
    float t1 = ds * w1[c] + b1[c];
    h[c] = t1 / (1.f + expf(-t1));
    __syncthreads();
    float e = b2[c];
    const float* w2r = w2 + c * C_;
    for (int j = 0; j < C_; j++) e += w2r[j] * h[j];
    __syncthreads();
    emb[c] = e;
    __syncthreads();
    float p = bp[c];
    const float* wpr = wp + c * C_;
    for (int j = 0; j < C_; j++) p += wpr[j] * emb[j];
    g_proj[b * C_ + c] = p;
}

__global__ void k_wtrans(const float* __restrict__ w_conv) {
    int i = blockIdx.x * 256 + threadIdx.x;
    if (i < 3 * C_ * O_) {
        int o = i % O_, c = (i / O_) % C_, k = i / (O_ * C_);
        g_wc[i] = w_conv[(o * C_ + c) * 3 + k];
    }
}

__global__ void k_w2build(const float* __restrict__ w_skip, const float* __restrict__ w_res) {
    int i = blockIdx.x * 256 + threadIdx.x;   // 512*512: (n, kk)
    int n = i >> 9, kk = i & 511;
    int c = kk & 255, part = kk >> 8;
    float wv = (n < 256) ? w_res[n * C_ + c] : w_skip[(n - 256) * C_ + c];
    g_w2[n * 512 + kk] = __float2half((part ? DZ : ZA) * wv);
}

__global__ void k_wsplit(const float* __restrict__ w_conv) {
    int i = blockIdx.x * 256 + threadIdx.x;    // 512*256 (o,c)
    int o = i >> 8, c = i & 255;
    #pragma unroll
    for (int k = 0; k < 3; k++) {
        float w = w_conv[(o * C_ + c) * 3 + k] * WSC;
        __half h1 = __float2half_rn(w);
        float r1 = w - __half2float(h1);
        __half h2 = __float2half_rn(r1);
        size_t base = ((size_t)k * 512 + o) * 256 + c;
        g_wcs[0 * 393216 + base] = h1;
        g_wcs[1 * 393216 + base] = h2;
    }
}

// x transpose+split: [tb][c][l] f32 -> [tb][l][hi|lo] fp16, scaled by 16
__global__ void k_xsplit(const float* __restrict__ x) {
    __shared__ float tile[32][33];
    int tb = blockIdx.z;
    int c0 = blockIdx.y * 32, l0 = blockIdx.x * 32;
    int tx = threadIdx.x & 31, ty = threadIdx.x >> 5;   // 32x8
    const float* xb = x + ((size_t)tb * C_ + c0) * L_ + l0;
    #pragma unroll
    for (int i = 0; i < 4; i++)
        tile[ty + i * 8][tx] = xb[(size_t)(ty + i * 8) * L_ + tx];
    __syncthreads();
    __half* dst = g_xt + ((size_t)tb * L_ + l0) * 512 + c0;
    #pragma unroll
    for (int i = 0; i < 4; i++) {
        int l = ty + i * 8;
        float v = tile[tx][l] * XS;
        __half h1 = __float2half_rn(v);
        __half h2 = __float2half_rn(v - __half2float(h1));
        dst[(size_t)l * 512 + tx] = h1;
        dst[(size_t)l * 512 + 256 + tx] = h2;
    }
}

__global__ void k_econv(const float* __restrict__ b_conv) {
    int b = blockIdx.x;
    int lo = threadIdx.x & 127;
    int half = threadIdx.x >> 7;
    int o = blockIdx.y * 128 + lo;
    __shared__ float pr[C_];
    __shared__ float red[3][128];
    for (int i = threadIdx.x; i < C_; i += 256) pr[i] = g_proj[b * C_ + i];
    __syncthreads();
    float e0 = 0.f, e1 = 0.f, e2 = 0.f;
    int c0 = half * 128;
    #pragma unroll 4
    for (int c = c0; c < c0 + 128; c++) {
        float p = pr[c];
        e0 += g_wc[(0 * C_ + c) * O_ + o] * p;
        e1 += g_wc[(1 * C_ + c) * O_ + o] * p;
        e2 += g_wc[(2 * C_ + c) * O_ + o] * p;
    }
    if (half) { red[0][lo] = e0; red[1][lo] = e1; red[2][lo] = e2; }
    __syncthreads();
    if (!half) {
        e0 += red[0][lo]; e1 += red[1][lo]; e2 += red[2][lo];
        g_base[b * O_ + o] = e0 + e1 + e2 + b_conv[o];
        g_e0[b * O_ + o] = e0;
        g_e2[b * O_ + o] = e2;
    }
}

// ---------------- conv1d + LIF via HMMA (fp16 2x2 split, 3 terms) ----------------
// 128-l tile, 512 threads, 1 CTA/SM. grid (16 lt, 4 ot, 16 b).
// stage: ws[6 q][128 m][24 halves] = 36864B ; xs[2 sp][130 l][24 halves] = 12480B
#define WS_SZ 36864
#define CSTAGE 49344
#define CONV_SMEM (2*CSTAGE + 2*18432)

__global__ void __launch_bounds__(512, 1) k_conv_mma() {
    extern __shared__ char sm[];
    const u32 sb = smem_u32(sm);
    const int lt = blockIdx.x, ot = blockIdx.y, b = blockIdx.z;
    const int l0 = lt * 128;
    const int tid = threadIdx.x, wid = tid >> 5, lane = tid & 31;
    const int wn = wid >> 2, wl = wid & 3;
    const int r4 = lane >> 2, c2 = (lane & 3) * 2;

    __half* su  = (__half*)(sm + 2 * CSTAGE);
    __half* sw_ = (__half*)(sm + 2 * CSTAGE + 18432);

    auto load_step = [&](int step) {
        int t = step >> 4, cc = (step & 15) << 4, s = step & 1;
        u32 wsb = sb + s * CSTAGE;
        // weights: 1536 cp16 (3 per thread); q = sh*2+sp
        #pragma unroll
        for (int j = 0; j < 3; j++) {
            int idx = tid + j * 512;
            int c16 = idx & 1;
            int m = (idx >> 1) & 127;
            int q = idx >> 8;              // 0..5
            int sh = q >> 1, sp = q & 1;
            int o = (m < 64) ? (ot * 64 + m) : (256 + ot * 64 + m - 64);
            const __half* src = g_wcs + (((size_t)(sp * 3 + sh) * 512 + o) << 8) + cc + c16 * 8;
            cp16(wsb + (u32)((q * 128 + m) * 48 + c16 * 16), src);
        }
        // x tile: 520 cp16 from presplit g_xt (zero-fill halo)
        const __half* xb = g_xt + ((size_t)(t * B_ + b) * L_) * 512;
        u32 xsb = sb + s * CSTAGE + WS_SZ;
        #pragma unroll
        for (int j = 0; j < 2; j++) {
            int u = tid + j * 512;
            if (u < 520) {
                int li = u >> 2, q = u & 3;
                int sp = q >> 1, h16 = q & 1;
                int gl = l0 - 1 + li;
                bool ok = (gl >= 0 && gl < L_);
                int glc = ok ? gl : 0;
                const __half* src = xb + (size_t)glc * 512 + sp * 256 + cc + h16 * 8;
                cp16z(xsb + (u32)(((sp * 130 + li) * 24 + h16 * 8) * 2), src, ok);
            }
        }
        asm volatile("cp.async.commit_group;" ::: "memory");
    };

    float acc[2][4][4];
    float v[2][2][8];
    #pragma unroll
    for (int m = 0; m < 2; m++)
        #pragma unroll
        for (int j = 0; j < 4; j++)
            #pragma unroll
            for (int e = 0; e < 4; e++) acc[m][j][e] = 0.f;
    #pragma unroll
    for (int g = 0; g < 2; g++)
        #pragma unroll
        for (int h = 0; h < 2; h++)
            #pragma unroll
            for (int e = 0; e < 8; e++) v[g][h][e] = 0.f;

    load_step(0);
    load_step(1);

    const __half one = __float2half(1.f), zero = __float2half(0.f);

    #pragma unroll 1
    for (int step = 0; step < 64; step++) {
        if (step < 62) asm volatile("cp.async.wait_group 1;" ::: "memory");
        else           asm volatile("cp.async.wait_group 0;" ::: "memory");
        __syncthreads();
        int s = step & 1;
        const char* wsb = sm + s * CSTAGE;
        const __half* xs = (const __half*)(sm + s * CSTAGE + WS_SZ);

        #pragma unroll
        for (int sh = 0; sh < 3; sh++) {
            u32 bf0[2][4], bf1[2][4];
            #pragma unroll
            for (int sp = 0; sp < 2; sp++)
                #pragma unroll
                for (int j = 0; j < 4; j++) {
                    const __half* p = xs + (sp * 130 + wl * 32 + j * 8 + r4 + sh) * 24 + c2;
                    bf0[sp][j] = *(const u32*)p;
                    bf1[sp][j] = *(const u32*)(p + 8);
                }
            u32 a[2][2][4];
            #pragma unroll
            for (int sp = 0; sp < 2; sp++)
                #pragma unroll
                for (int m = 0; m < 2; m++) {
                    const __half* p = (const __half*)(wsb + ((sh * 2 + sp) * 128 + m * 64 + wn * 16 + r4) * 48) + c2;
                    a[sp][m][0] = *(const u32*)p;
                    a[sp][m][1] = *(const u32*)(p + 8 * 24);
                    a[sp][m][2] = *(const u32*)(p + 8);
                    a[sp][m][3] = *(const u32*)(p + 8 * 24 + 8);
                }
            #pragma unroll
            for (int m = 0; m < 2; m++)
                #pragma unroll
                for (int j = 0; j < 4; j++) {
                    #define TRM(xi, wi) mma16816(acc[m][j], a[wi][m][0], a[wi][m][1], a[wi][m][2], a[wi][m][3], bf0[xi][j], bf1[xi][j])
                    TRM(0, 0); TRM(0, 1); TRM(1, 0);
                    #undef TRM
                }
        }
        __syncthreads();
        if (step + 2 < 64) load_step(step + 2);

        if ((step & 15) == 15) {   // epilogue for this t
            int t = step >> 4;
            int chb = ot * 64 + wn * 16 + r4;
            #pragma unroll
            for (int h = 0; h < 2; h++) {
                int cg = chb + h * 8;
                int cf = cg + 256;
                float bg0 = g_base[b * O_ + cg], bf0v = g_base[b * O_ + cf];
                float e0g = g_e0[b * O_ + cg], e0f = g_e0[b * O_ + cf];
                float e2g = g_e2[b * O_ + cg], e2f = g_e2[b * O_ + cf];
                #pragma unroll
                for (int j = 0; j < 4; j++)
                    #pragma unroll
                    for (int e = 0; e < 2; e++) {
                        int ll = wl * 32 + j * 8 + c2 + e;
                        int gl = l0 + ll;
                        float bg = bg0, bfv = bf0v;
                        if (gl == 0)      { bg -= e0g; bfv -= e0f; }
                        if (gl == L_ - 1) { bg -= e2g; bfv -= e2f; }
                        float yg = acc[0][j][h * 2 + e] * INV_SC + bg;
                        float yf = acc[1][j][h * 2 + e] * INV_SC + bfv;
                        int vi = j * 2 + e;
                        float vg = v[0][h][vi]; vg = vg + (yg - vg) / 1.2f;
                        float vf = v[1][h][vi]; vf = vf + (yf - vf) / 1.2f;
                        bool sg = vg >= 0.5f, sf = vf >= 0.5f;
                        v[0][h][vi] = sg ? 0.f : vg;
                        v[1][h][vi] = sf ? 0.f : vf;
                        su[ll * 72 + wn * 16 + r4 + h * 8] = sf ? one : zero;
                        sw_[ll * 72 + wn * 16 + r4 + h * 8] = (sf && sg) ? one : zero;
                    }
            }
            #pragma unroll
            for (int m = 0; m < 2; m++)
                #pragma unroll
                for (int j = 0; j < 4; j++)
                    #pragma unroll
                    for (int e = 0; e < 4; e++) acc[m][j][e] = 0.f;
            __syncthreads();
            {
                int row = tid >> 2, seg = tid & 3;   // 128 rows
                __half* dst = g_s + ((size_t)(t * B_ + b) * L_ + l0 + row) * 512;
                uint4 a0 = *(uint4*)&su[row * 72 + seg * 16];
                uint4 a1 = *(uint4*)&su[row * 72 + seg * 16 + 8];
                uint4 b0 = *(uint4*)&sw_[row * 72 + seg * 16];
                uint4 b1 = *(uint4*)&sw_[row * 72 + seg * 16 + 8];
                *(uint4*)(dst + ot * 64 + seg * 16)           = a0;
                *(uint4*)(dst + ot * 64 + seg * 16 + 8)       = a1;
                *(uint4*)(dst + 256 + ot * 64 + seg * 16)     = b0;
                *(uint4*)(dst + 256 + ot * 64 + seg * 16 + 8) = b1;
            }
            __syncthreads();
        }
    }
}

// ---------------- output GEMM via mma.sync (HMMA), single split ----------------
#define SMEM_OUT 40960
#define RS 40

__global__ void __launch_bounds__(256) k_out_mma(const float* __restrict__ x,
                                                 const float* __restrict__ b_skip,
                                                 const float* __restrict__ b_res,
                                                 float* __restrict__ out) {
    extern __shared__ __half smo[];
    const int lt = blockIdx.x, nt = blockIdx.y, tb = blockIdx.z;
    const int tid = threadIdx.x;
    const int wid = tid >> 5, lane = tid & 31;
    const int wn = wid >> 1;
    const int wl = wid & 1;
    const u32 sb = smem_u32(smo);

    const __half* gS = g_s + ((size_t)tb * L_ + lt * 128) * 512;
    const __half* gW = g_w2 + (size_t)(nt * 128) * 512;

    float acc[2][8][4];
    #pragma unroll
    for (int m = 0; m < 2; m++)
        #pragma unroll
        for (int j = 0; j < 8; j++)
            #pragma unroll
            for (int e = 0; e < 4; e++) acc[m][j][e] = 0.f;

    auto load_chunk = [&](int c) {
        int s = c & 1;
        int k0 = c * 32;
        u32 sS = sb + s * 10240;
        u32 sH = sb + 20480 + s * 10240;
        #pragma unroll
        for (int j = 0; j < 2; j++) {
            int vv = tid + j * 256;           // 0..511
            int r = vv >> 2, c16 = vv & 3;
            u32 doff = (u32)(r * RS + c16 * 8) * 2;
            cp16(sS + doff, gS + (size_t)r * 512 + k0 + c16 * 8);
            cp16(sH + doff, gW + (size_t)r * 512 + k0 + c16 * 8);
        }
        asm volatile("cp.async.commit_group;" ::: "memory");
    };

    load_chunk(0);
    load_chunk(1);

    const int r4 = lane >> 2, c2 = 2 * (lane & 3);

    #pragma unroll 1
    for (int c = 0; c < 16; c++) {
        if (c + 2 < 16) asm volatile("cp.async.wait_group 1;" ::: "memory");
        else            asm volatile("cp.async.wait_group 0;" ::: "memory");
        __syncthreads();
        int s = c & 1;
        const __half* S  = smo + s * 5120;
        const __half* WH = smo + 10240 + s * 5120;

        #pragma unroll
        for (int ks = 0; ks < 2; ks++) {
            int k0s = ks * 16;
            u32 bs0[8], bs1[8];
            #pragma unroll
            for (int j = 0; j < 8; j++) {
                int l = wl * 64 + j * 8 + r4;
                const __half* p = S + l * RS + k0s + c2;
                bs0[j] = *(const u32*)p;
                bs1[j] = *(const u32*)(p + 8);
            }
            #pragma unroll
            for (int m = 0; m < 2; m++) {
                int row = wn * 32 + m * 16 + r4;
                const __half* p = WH + row * RS + k0s + c2;
                u32 a0 = *(const u32*)p;
                u32 a1 = *(const u32*)(p + 8 * RS);
                u32 a2 = *(const u32*)(p + 8);
                u32 a3 = *(const u32*)(p + 8 * RS + 8);
                #pragma unroll
                for (int j = 0; j < 8; j++)
                    mma16816(acc[m][j], a0, a1, a2, a3, bs0[j], bs1[j]);
            }
        }
        __syncthreads();
        if (c + 2 < 16) load_chunk(c + 2);
    }

    size_t base_tb = (size_t)tb * C_ * L_;
    #pragma unroll
    for (int m = 0; m < 2; m++) {
        #pragma unroll
        for (int j = 0; j < 8; j++) {
            int lg = lt * 128 + wl * 64 + j * 8 + c2;
            #pragma unroll
            for (int half = 0; half < 2; half++) {
                int ng = nt * 128 + wn * 32 + m * 16 + r4 + half * 8;
                float v0 = acc[m][j][half * 2], v1 = acc[m][j][half * 2 + 1];
                if (ng < 256) {
                    size_t idx = base_tb + (size_t)ng * L_ + lg;
                    float bias = b_res[ng];
                    float2 xv = *(const float2*)(x + idx);
                    *(float2*)(out + idx) = make_float2(v0 + xv.x + bias, v1 + xv.y + bias);
                } else {
                    int o = ng - 256;
                    size_t idx = base_tb + (size_t)o * L_ + lg;
                    float bias = b_skip[o];
                    *(float2*)(out + TBCL_ + idx) = make_float2(v0 + bias, v1 + bias);
                }
            }
        }
    }
}

extern "C" void kernel_launch(void* const* d_in, const int* in_sizes, int n_in,
                              void* d_out, int out_size) {
    const float* x      = (const float*)d_in[0];
    const int*   dstep  = (const int*)d_in[1];
    const float* w_emb1 = (const float*)d_in[2];
    const float* b_emb1 = (const float*)d_in[3];
    const float* w_emb2 = (const float*)d_in[4];
    const float* b_emb2 = (const float*)d_in[5];
    const float* w_proj = (const float*)d_in[6];
    const float* b_proj = (const float*)d_in[7];
    const float* w_conv = (const float*)d_in[8];
    const float* b_conv = (const float*)d_in[9];
    const float* w_skip = (const float*)d_in[10];
    const float* b_skip = (const float*)d_in[11];
    const float* w_res  = (const float*)d_in[12];
    const float* b_res  = (const float*)d_in[13];
    float* out = (float*)d_out;

    static int attr_set = 0;
    if (!attr_set) {
        cudaFuncSetAttribute(k_out_mma, cudaFuncAttributeMaxDynamicSharedMemorySize, SMEM_OUT);
        cudaFuncSetAttribute(k_conv_mma, cudaFuncAttributeMaxDynamicSharedMemorySize, CONV_SMEM);
        attr_set = 1;
    }

    k_proj<<<B_, C_>>>(dstep, w_emb1, b_emb1, w_emb2, b_emb2, w_proj, b_proj);
    k_wtrans<<<(3 * C_ * O_ + 255) / 256, 256>>>(w_conv);
    k_w2build<<<512 * 512 / 256, 256>>>(w_skip, w_res);
    k_wsplit<<<512 * 256 / 256, 256>>>(w_conv);
    k_xsplit<<<dim3(L_ / 32, C_ / 32, T_ * B_), 256>>>(x);
    k_econv<<<dim3(B_, O_ / 128), 256>>>(b_conv);
    k_conv_mma<<<dim3(16, 4, 16), 512, CONV_SMEM>>>();
    k_out_mma<<<dim3(16, 4, 64), 256, SMEM_OUT>>>(x, b_skip, b_res, out);
}